// round 1
// baseline (speedup 1.0000x reference)
#include <cuda_runtime.h>
#include <math.h>

// Problem constants
#define Bb 2
#define Ss 2048
#define DM 1024
#define Hh 16
#define Dd 64
#define Nn (Bb*Ss)          // 4096 tokens
#define BH (Bb*Hh)          // 32

// Scratch (device globals: no allocation allowed)
__device__ float g_Q[Bb*Hh*Ss*Dd];   // [b][h][s][d]
__device__ float g_K[Bb*Hh*Ss*Dd];
__device__ float g_V[Bb*Hh*Ss*Dd];
__device__ float g_AO[Nn*DM];        // attention output, [b][s][h*64+d] = [n][1024]

// ---------------------------------------------------------------------------
// Fused QKV projection: Y = X @ W + b, scattered to [b][h][s][d] layout.
// Classic 128x128x8 SGEMM, 256 threads, 8x8 per-thread register tile.
// blockIdx.z selects {Q,K,V}.
// ---------------------------------------------------------------------------
__global__ __launch_bounds__(256, 2)
void qkv_gemm_kernel(const float* __restrict__ x,
                     const float* __restrict__ wq, const float* __restrict__ bq,
                     const float* __restrict__ wk, const float* __restrict__ bk,
                     const float* __restrict__ wv, const float* __restrict__ bv)
{
    __shared__ float As[8][128];   // As[k][m]  (X tile, transposed)
    __shared__ float Bs[8][128];   // Bs[k][n]  (W tile)

    const float* W; const float* bias; float* out;
    if (blockIdx.z == 0)      { W = wq; bias = bq; out = g_Q; }
    else if (blockIdx.z == 1) { W = wk; bias = bk; out = g_K; }
    else                      { W = wv; bias = bv; out = g_V; }

    const int tid  = threadIdx.x;
    const int tx   = tid & 15;       // col group
    const int ty   = tid >> 4;       // row group
    const int row0 = blockIdx.y * 128;
    const int col0 = blockIdx.x * 128;

    const int arow = tid >> 1;            // 0..127
    const int acol = (tid & 1) * 4;       // 0 or 4
    const int brow = tid >> 5;            // 0..7
    const int bcol = (tid & 31) * 4;      // 0..124

    float acc[8][8];
#pragma unroll
    for (int i = 0; i < 8; i++)
#pragma unroll
        for (int j = 0; j < 8; j++) acc[i][j] = 0.f;

    for (int k0 = 0; k0 < DM; k0 += 8) {
        float4 av = *(const float4*)&x[(size_t)(row0 + arow) * DM + k0 + acol];
        float4 bv4 = *(const float4*)&W[(size_t)(k0 + brow) * DM + col0 + bcol];
        As[acol + 0][arow] = av.x;
        As[acol + 1][arow] = av.y;
        As[acol + 2][arow] = av.z;
        As[acol + 3][arow] = av.w;
        *(float4*)&Bs[brow][bcol] = bv4;
        __syncthreads();
#pragma unroll
        for (int k = 0; k < 8; k++) {
            float a[8], bb[8];
            *(float4*)&a[0]  = *(float4*)&As[k][ty * 8];
            *(float4*)&a[4]  = *(float4*)&As[k][ty * 8 + 4];
            *(float4*)&bb[0] = *(float4*)&Bs[k][tx * 8];
            *(float4*)&bb[4] = *(float4*)&Bs[k][tx * 8 + 4];
#pragma unroll
            for (int i = 0; i < 8; i++)
#pragma unroll
                for (int j = 0; j < 8; j++)
                    acc[i][j] = fmaf(a[i], bb[j], acc[i][j]);
        }
        __syncthreads();
    }

    // Epilogue: add bias, scatter to [b][h][s][d]
#pragma unroll
    for (int i = 0; i < 8; i++) {
        const int n = row0 + ty * 8 + i;
        const int b = n >> 11;
        const int s = n & 2047;
#pragma unroll
        for (int j = 0; j < 8; j++) {
            const int m = col0 + tx * 8 + j;
            const int h = m >> 6;
            const int d = m & 63;
            out[(((size_t)(b * Hh + h)) * Ss + s) * Dd + d] = acc[i][j] + bias[m];
        }
    }
}

// ---------------------------------------------------------------------------
// RoPE applied in-place to g_Q and g_K. One thread per (bh, s, freq-pair).
// ---------------------------------------------------------------------------
__global__ void rope_kernel()
{
    int idx = blockIdx.x * blockDim.x + threadIdx.x;   // BH*S*32 threads
    if (idx >= BH * Ss * 32) return;
    const int j  = idx & 31;
    const int s  = (idx >> 5) & (Ss - 1);
    const int bh = idx >> 16;   // idx / (32*2048)

    const float inv = powf(10000.f, -(float)j / 32.f);
    const float ang = (float)s * inv;
    float sn, cs;
    sincosf(ang, &sn, &cs);

    const size_t base = ((size_t)bh * Ss + s) * Dd;
    float q1 = g_Q[base + j], q2 = g_Q[base + j + 32];
    g_Q[base + j]      = q1 * cs - q2 * sn;
    g_Q[base + j + 32] = q2 * cs + q1 * sn;
    float k1 = g_K[base + j], k2 = g_K[base + j + 32];
    g_K[base + j]      = k1 * cs - k2 * sn;
    g_K[base + j + 32] = k2 * cs + k1 * sn;
}

// ---------------------------------------------------------------------------
// Flash attention: Q-tile 128, K-tile 64, 256 threads.
// Thread (tx,ty): owns 8 query rows (ty*8..) and 4 cols (tx*4..) of each
// score/output tile. Online softmax with shfl reductions over the 16-lane
// tx group (half-warp).
// ---------------------------------------------------------------------------
#define SQT_STRIDE 132   // sQt row stride (multiple of 4, breaks bank align)
#define SKT_STRIDE 68
#define SV_STRIDE  68
#define SPT_STRIDE 131   // odd stride: conflict-light scalar P access
#define ATTN_SMEM_FLOATS (64*SQT_STRIDE + 64*SKT_STRIDE + 64*SV_STRIDE + 64*SPT_STRIDE)
#define ATTN_SMEM_BYTES  (ATTN_SMEM_FLOATS * 4)

__global__ __launch_bounds__(256, 2)
void attn_kernel()
{
    extern __shared__ float sm[];
    float* sQt = sm;                        // [d][r]  64 x (128+4)
    float* sKt = sQt + 64 * SQT_STRIDE;     // [d][c]  64 x (64+4)
    float* sV  = sKt + 64 * SKT_STRIDE;     // [k][d]  64 x (64+4)
    float* sPt = sV  + 64 * SV_STRIDE;      // [k][r]  64 x 131

    const int tid = threadIdx.x;
    const int tx  = tid & 15;
    const int ty  = tid >> 4;
    const int qt  = blockIdx.x;     // 0..15
    const int bh  = blockIdx.y;     // 0..31
    const int b   = bh >> 4;
    const int h   = bh & 15;

    const float* Qg = g_Q + ((size_t)bh * Ss + qt * 128) * Dd;
    const float* Kg = g_K + (size_t)bh * Ss * Dd;
    const float* Vg = g_V + (size_t)bh * Ss * Dd;

    // Load Q tile, scaled by 1/sqrt(64), transposed to [d][r]
    {
        const int qr = tid >> 1;
        const int d0 = (tid & 1) * 32;
#pragma unroll
        for (int v = 0; v < 8; v++) {
            const int d = d0 + v * 4;
            float4 q = *(const float4*)&Qg[(size_t)qr * Dd + d];
            sQt[(d + 0) * SQT_STRIDE + qr] = q.x * 0.125f;
            sQt[(d + 1) * SQT_STRIDE + qr] = q.y * 0.125f;
            sQt[(d + 2) * SQT_STRIDE + qr] = q.z * 0.125f;
            sQt[(d + 3) * SQT_STRIDE + qr] = q.w * 0.125f;
        }
    }

    float m_i[8], l_i[8], o_acc[8][4];
#pragma unroll
    for (int i = 0; i < 8; i++) {
        m_i[i] = -1e30f; l_i[i] = 0.f;
#pragma unroll
        for (int j = 0; j < 4; j++) o_acc[i][j] = 0.f;
    }

    const int kr  = tid >> 2;         // 0..63
    const int kd0 = (tid & 3) * 16;   // 0,16,32,48

    for (int kt = 0; kt < 32; kt++) {
        __syncthreads();  // previous P·V done before overwriting K/V
        // Load K tile (transposed) and V tile
#pragma unroll
        for (int v = 0; v < 4; v++) {
            const int d = kd0 + v * 4;
            float4 kk = *(const float4*)&Kg[((size_t)(kt * 64 + kr)) * Dd + d];
            sKt[(d + 0) * SKT_STRIDE + kr] = kk.x;
            sKt[(d + 1) * SKT_STRIDE + kr] = kk.y;
            sKt[(d + 2) * SKT_STRIDE + kr] = kk.z;
            sKt[(d + 3) * SKT_STRIDE + kr] = kk.w;
            *(float4*)&sV[kr * SV_STRIDE + d] =
                *(const float4*)&Vg[((size_t)(kt * 64 + kr)) * Dd + d];
        }
        __syncthreads();

        // S = (Q/8) @ K^T   (8 rows x 4 cols per thread)
        float sacc[8][4];
#pragma unroll
        for (int i = 0; i < 8; i++)
#pragma unroll
            for (int j = 0; j < 4; j++) sacc[i][j] = 0.f;

#pragma unroll 8
        for (int d = 0; d < 64; d++) {
            float qa[8], kb[4];
            *(float4*)&qa[0] = *(float4*)&sQt[d * SQT_STRIDE + ty * 8];
            *(float4*)&qa[4] = *(float4*)&sQt[d * SQT_STRIDE + ty * 8 + 4];
            *(float4*)&kb[0] = *(float4*)&sKt[d * SKT_STRIDE + tx * 4];
#pragma unroll
            for (int i = 0; i < 8; i++)
#pragma unroll
                for (int j = 0; j < 4; j++)
                    sacc[i][j] = fmaf(qa[i], kb[j], sacc[i][j]);
        }

        // Online softmax update + write P (transposed [k][r]) to smem
#pragma unroll
        for (int i = 0; i < 8; i++) {
            float rmax = fmaxf(fmaxf(sacc[i][0], sacc[i][1]),
                               fmaxf(sacc[i][2], sacc[i][3]));
            rmax = fmaxf(rmax, __shfl_xor_sync(0xffffffffu, rmax, 8));
            rmax = fmaxf(rmax, __shfl_xor_sync(0xffffffffu, rmax, 4));
            rmax = fmaxf(rmax, __shfl_xor_sync(0xffffffffu, rmax, 2));
            rmax = fmaxf(rmax, __shfl_xor_sync(0xffffffffu, rmax, 1));
            const float m_new = fmaxf(m_i[i], rmax);
            const int r = ty * 8 + i;
            float rs = 0.f;
#pragma unroll
            for (int j = 0; j < 4; j++) {
                float p = __expf(sacc[i][j] - m_new);
                sPt[(tx * 4 + j) * SPT_STRIDE + r] = p;
                rs += p;
            }
            rs += __shfl_xor_sync(0xffffffffu, rs, 8);
            rs += __shfl_xor_sync(0xffffffffu, rs, 4);
            rs += __shfl_xor_sync(0xffffffffu, rs, 2);
            rs += __shfl_xor_sync(0xffffffffu, rs, 1);
            const float sc = __expf(m_i[i] - m_new);
            l_i[i] = l_i[i] * sc + rs;
            m_i[i] = m_new;
#pragma unroll
            for (int j = 0; j < 4; j++) o_acc[i][j] *= sc;
        }
        __syncthreads();

        // O_acc += P @ V
#pragma unroll 8
        for (int k = 0; k < 64; k++) {
            float pa[8], vb[4];
#pragma unroll
            for (int i = 0; i < 8; i++)
                pa[i] = sPt[k * SPT_STRIDE + ty * 8 + i];
            *(float4*)&vb[0] = *(float4*)&sV[k * SV_STRIDE + tx * 4];
#pragma unroll
            for (int i = 0; i < 8; i++)
#pragma unroll
                for (int j = 0; j < 4; j++)
                    o_acc[i][j] = fmaf(pa[i], vb[j], o_acc[i][j]);
        }
    }

    // Epilogue: normalize and write to [b][s][h*64+d]
#pragma unroll
    for (int i = 0; i < 8; i++) {
        const float inv = 1.f / l_i[i];
        const int srow = qt * 128 + ty * 8 + i;
        float4 v;
        v.x = o_acc[i][0] * inv;
        v.y = o_acc[i][1] * inv;
        v.z = o_acc[i][2] * inv;
        v.w = o_acc[i][3] * inv;
        *(float4*)&g_AO[((size_t)b * Ss + srow) * DM + h * 64 + tx * 4] = v;
    }
}

// ---------------------------------------------------------------------------
// Output projection: out = AO @ wo + bo (row-major result)
// ---------------------------------------------------------------------------
__global__ __launch_bounds__(256, 2)
void oproj_kernel(const float* __restrict__ wo, const float* __restrict__ bo,
                  float* __restrict__ out)
{
    __shared__ float As[8][128];
    __shared__ float Bs[8][128];

    const int tid  = threadIdx.x;
    const int tx   = tid & 15;
    const int ty   = tid >> 4;
    const int row0 = blockIdx.y * 128;
    const int col0 = blockIdx.x * 128;

    const int arow = tid >> 1;
    const int acol = (tid & 1) * 4;
    const int brow = tid >> 5;
    const int bcol = (tid & 31) * 4;

    float acc[8][8];
#pragma unroll
    for (int i = 0; i < 8; i++)
#pragma unroll
        for (int j = 0; j < 8; j++) acc[i][j] = 0.f;

    for (int k0 = 0; k0 < DM; k0 += 8) {
        float4 av  = *(const float4*)&g_AO[(size_t)(row0 + arow) * DM + k0 + acol];
        float4 bv4 = *(const float4*)&wo[(size_t)(k0 + brow) * DM + col0 + bcol];
        As[acol + 0][arow] = av.x;
        As[acol + 1][arow] = av.y;
        As[acol + 2][arow] = av.z;
        As[acol + 3][arow] = av.w;
        *(float4*)&Bs[brow][bcol] = bv4;
        __syncthreads();
#pragma unroll
        for (int k = 0; k < 8; k++) {
            float a[8], bb[8];
            *(float4*)&a[0]  = *(float4*)&As[k][ty * 8];
            *(float4*)&a[4]  = *(float4*)&As[k][ty * 8 + 4];
            *(float4*)&bb[0] = *(float4*)&Bs[k][tx * 8];
            *(float4*)&bb[4] = *(float4*)&Bs[k][tx * 8 + 4];
#pragma unroll
            for (int i = 0; i < 8; i++)
#pragma unroll
                for (int j = 0; j < 8; j++)
                    acc[i][j] = fmaf(a[i], bb[j], acc[i][j]);
        }
        __syncthreads();
    }

#pragma unroll
    for (int i = 0; i < 8; i++) {
        const int n = row0 + ty * 8 + i;
#pragma unroll
        for (int jv = 0; jv < 2; jv++) {
            const int m = col0 + tx * 8 + jv * 4;
            float4 v;
            v.x = acc[i][jv * 4 + 0] + bo[m + 0];
            v.y = acc[i][jv * 4 + 1] + bo[m + 1];
            v.z = acc[i][jv * 4 + 2] + bo[m + 2];
            v.w = acc[i][jv * 4 + 3] + bo[m + 3];
            *(float4*)&out[(size_t)n * DM + m] = v;
        }
    }
}

// ---------------------------------------------------------------------------
extern "C" void kernel_launch(void* const* d_in, const int* in_sizes, int n_in,
                              void* d_out, int out_size)
{
    const float* x  = (const float*)d_in[0];
    const float* wq = (const float*)d_in[1];
    const float* bq = (const float*)d_in[2];
    const float* wk = (const float*)d_in[3];
    const float* bk = (const float*)d_in[4];
    const float* wv = (const float*)d_in[5];
    const float* bv = (const float*)d_in[6];
    const float* wo = (const float*)d_in[7];
    const float* bo = (const float*)d_in[8];
    float* out = (float*)d_out;

    cudaFuncSetAttribute(attn_kernel,
                         cudaFuncAttributeMaxDynamicSharedMemorySize,
                         ATTN_SMEM_BYTES);

    // 1) QKV projections + scatter to head-major
    qkv_gemm_kernel<<<dim3(DM / 128, Nn / 128, 3), 256>>>(x, wq, bq, wk, bk, wv, bv);
    // 2) RoPE on Q, K
    rope_kernel<<<(BH * Ss * 32) / 256, 256>>>();
    // 3) Flash attention
    attn_kernel<<<dim3(Ss / 128, BH), 256, ATTN_SMEM_BYTES>>>();
    // 4) Output projection
    oproj_kernel<<<dim3(DM / 128, Nn / 128), 256>>>(wo, bo, out);
}

// round 3
// speedup vs baseline: 1.3155x; 1.3155x over previous
#include <cuda_runtime.h>
#include <cuda_bf16.h>
#include <math.h>
#include <stdint.h>

// Problem constants
#define Bb 2
#define Ss 2048
#define DM 1024
#define Hh 16
#define Dd 64
#define Nn (Bb*Ss)          // 4096 tokens
#define BH (Bb*Hh)          // 32

// Scratch (device globals: no allocation allowed)
__device__ float g_Q[Bb*Hh*Ss*Dd];   // [b][h][s][d]
__device__ float g_K[Bb*Hh*Ss*Dd];
__device__ float g_V[Bb*Hh*Ss*Dd];
__device__ float g_AO[Nn*DM];        // attention output, [b][s][h*64+d]

// bf16 hi/lo split buffers
__device__ __nv_bfloat16 g_Ahi[Nn*DM], g_Alo[Nn*DM];          // activations (x, then AO)
__device__ __nv_bfloat16 g_Whi[4][DM*DM], g_Wlo[4][DM*DM];    // wq, wk, wv, wo

// ===========================================================================
// PTX helpers (generic-PTX safe: mma.sync / ldmatrix / cp.async only)
// ===========================================================================
__device__ __forceinline__ uint32_t smem_u32(const void* p) {
    uint32_t a;
    asm("{ .reg .u64 t; cvta.to.shared.u64 t, %1; cvt.u32.u64 %0, t; }"
        : "=r"(a) : "l"(p));
    return a;
}

#define CP_ASYNC16(dst, src) \
    asm volatile("cp.async.cg.shared.global [%0], [%1], 16;" \
                 :: "r"(dst), "l"(src) : "memory")
#define CP_COMMIT() asm volatile("cp.async.commit_group;" ::: "memory")
#define CP_WAIT(n)  asm volatile("cp.async.wait_group %0;" :: "n"(n) : "memory")

__device__ __forceinline__ void ldsm_x4(uint32_t* r, uint32_t addr) {
    asm volatile("ldmatrix.sync.aligned.m8n8.x4.shared.b16 {%0,%1,%2,%3}, [%4];"
                 : "=r"(r[0]), "=r"(r[1]), "=r"(r[2]), "=r"(r[3]) : "r"(addr));
}
__device__ __forceinline__ void ldsm_x4_t(uint32_t* r, uint32_t addr) {
    asm volatile("ldmatrix.sync.aligned.m8n8.x4.trans.shared.b16 {%0,%1,%2,%3}, [%4];"
                 : "=r"(r[0]), "=r"(r[1]), "=r"(r[2]), "=r"(r[3]) : "r"(addr));
}
__device__ __forceinline__ void mma_bf16(float* c, const uint32_t* a,
                                         const uint32_t* b) {
    asm volatile(
        "mma.sync.aligned.m16n8k16.row.col.f32.bf16.bf16.f32 "
        "{%0,%1,%2,%3}, {%4,%5,%6,%7}, {%8,%9}, {%0,%1,%2,%3};"
        : "+f"(c[0]), "+f"(c[1]), "+f"(c[2]), "+f"(c[3])
        : "r"(a[0]), "r"(a[1]), "r"(a[2]), "r"(a[3]), "r"(b[0]), "r"(b[1]));
}

// ===========================================================================
// Split fp32 -> bf16 hi + lo
// ===========================================================================
__global__ void split_kernel(const float* __restrict__ src,
                             __nv_bfloat16* __restrict__ hi,
                             __nv_bfloat16* __restrict__ lo, int n4)
{
    int i = blockIdx.x * blockDim.x + threadIdx.x;
    if (i >= n4) return;
    float4 f = ((const float4*)src)[i];
    __nv_bfloat16 h[4], l[4];
    float v[4] = {f.x, f.y, f.z, f.w};
#pragma unroll
    for (int j = 0; j < 4; j++) {
        h[j] = __float2bfloat16(v[j]);
        l[j] = __float2bfloat16(v[j] - __bfloat162float(h[j]));
    }
    ((uint2*)hi)[i] = *(uint2*)h;
    ((uint2*)lo)[i] = *(uint2*)l;
}

// ===========================================================================
// bf16-split GEMM via mma.sync: out = A[4096,1024] @ W[1024,1024] + bias
// Block tile 128x128, K-chunk 32, double-buffered cp.async smem.
// 8 warps: warp grid 4(m) x 2(n); warp tile 32 x 64 (one full head wide).
// mode: 0/1 = Q/K (rope+scatter), 2 = V (scatter), 3 = O (row-major)
//
// smem per stage (32KB):
//   sA: 128 rows x 128B.  unit u in [0,8): u0-3 = hi k(0..31), u4-7 = lo.
//       phys unit = u ^ (row & 7)                (conflict-free ldmatrix)
//   sB: [hi | lo], each 32 k-rows x 256B (n = 128). unit u in [0,16):
//       phys = (u&8) | ((u&7) ^ (krow&7))
// ===========================================================================
#define GSTAGE 32768
#define GEMM_SMEM (2*GSTAGE)

__global__ __launch_bounds__(256, 1)
void gemm_bf16split(const __nv_bfloat16* __restrict__ Ahi,
                    const __nv_bfloat16* __restrict__ Alo,
                    const __nv_bfloat16* __restrict__ Whi,
                    const __nv_bfloat16* __restrict__ Wlo,
                    const float* __restrict__ bias,
                    float* __restrict__ out, int mode)
{
    extern __shared__ __align__(1024) char sm[];
    const uint32_t sb = smem_u32(sm);
    const int tid  = threadIdx.x;
    const int wid  = tid >> 5;
    const int lane = tid & 31;
    const int wm   = wid >> 1;            // 0..3  (m-tile of 32)
    const int wn   = wid & 1;             // 0..1  (n-tile of 64 = one head)
    const int row0 = blockIdx.y * 128;
    const int col0 = blockIdx.x * 128;

    // --- cp.async source/dest precompute -----------------------------------
    // A: thread t covers row r = t>>1, units u = (t&1)*4 + i (i<4)
    const int a_r  = tid >> 1;
    const int a_u0 = (tid & 1) * 4;
    // B: arr = t>>7 (0=hi,1=lo), r = (t&127)>>2, u = (t&3)*4 + i
    const int b_arr = tid >> 7;
    const int b_r   = (tid & 127) >> 2;
    const int b_u0  = (tid & 3) * 4;

    const __nv_bfloat16* a_src_base =
        (a_u0 ? Alo : Ahi) + (size_t)(row0 + a_r) * DM;
    const __nv_bfloat16* b_src_base =
        (b_arr ? Wlo : Whi) + (size_t)b_r * DM + col0;

    uint32_t a_dst[4], b_dst[4];
#pragma unroll
    for (int i = 0; i < 4; i++) {
        const int au = a_u0 + i;
        a_dst[i] = (uint32_t)(a_r * 128 + ((au ^ (a_r & 7)) & 7) * 16
                              + ((au & 8) ? 128 : 0));  // au<8 always; no-op
        const int bu = b_u0 + i;
        b_dst[i] = (uint32_t)(16384 + b_arr * 8192 + b_r * 256
                              + (((bu & 8) | ((bu & 7) ^ (b_r & 7)))) * 16);
    }

    // --- ldmatrix address offsets ------------------------------------------
    const int q  = lane >> 3;
    const int rr = lane & 7;
    // A frags: row within block, per (mi, s)
    uint32_t offA[2][2][2];   // [hi/lo][s][mi]
#pragma unroll
    for (int s = 0; s < 2; s++)
#pragma unroll
        for (int mi = 0; mi < 2; mi++) {
            const int arow = wm * 32 + mi * 16 + (q & 1) * 8 + rr;
            const int uh = 2 * s + (q >> 1);
            const int ul = 4 + 2 * s + (q >> 1);
            offA[0][s][mi] = (uint32_t)(arow * 128 + (uh ^ (arow & 7)) * 16);
            offA[1][s][mi] = (uint32_t)(arow * 128 + (ul ^ (arow & 7)) * 16);
        }
    // B frags: per (arr, s, ng)
    uint32_t offB[2][2][4];
#pragma unroll
    for (int s = 0; s < 2; s++)
#pragma unroll
        for (int ng = 0; ng < 4; ng++) {
            const int krow = 16 * s + (q & 1) * 8 + rr;
            const int u = wn * 8 + ng * 2 + (q >> 1);
            const uint32_t sw = (uint32_t)(((u & 8) | ((u & 7) ^ (krow & 7))) * 16);
            offB[0][s][ng] = (uint32_t)(16384 + krow * 256 + sw);
            offB[1][s][ng] = (uint32_t)(16384 + 8192 + krow * 256 + sw);
        }

    float acc[2][8][4];
#pragma unroll
    for (int mi = 0; mi < 2; mi++)
#pragma unroll
        for (int nf = 0; nf < 8; nf++)
#pragma unroll
            for (int e = 0; e < 4; e++) acc[mi][nf][e] = 0.f;

    // --- prologue: load chunk 0 --------------------------------------------
    {
        const uint32_t st = sb;
#pragma unroll
        for (int i = 0; i < 4; i++) {
            const int au = a_u0 + i;
            CP_ASYNC16(st + a_dst[i], a_src_base + (au & 3) * 8);
            CP_ASYNC16(st + b_dst[i], b_src_base + (b_u0 + i) * 8);
        }
        CP_COMMIT();
    }

    for (int c = 0; c < 32; c++) {
        if (c + 1 < 32) {
            const uint32_t st = sb + ((c + 1) & 1) * GSTAGE;
            const int k0 = (c + 1) * 32;
#pragma unroll
            for (int i = 0; i < 4; i++) {
                const int au = a_u0 + i;
                CP_ASYNC16(st + a_dst[i], a_src_base + k0 + (au & 3) * 8);
                CP_ASYNC16(st + b_dst[i], b_src_base + (size_t)k0 * DM + (b_u0 + i) * 8);
            }
            CP_COMMIT();
            CP_WAIT(1);
        } else {
            CP_WAIT(0);
        }
        __syncthreads();

        const uint32_t st = sb + (c & 1) * GSTAGE;
#pragma unroll
        for (int s = 0; s < 2; s++) {
            uint32_t ah[2][4], al[2][4];
#pragma unroll
            for (int mi = 0; mi < 2; mi++) {
                ldsm_x4(ah[mi], st + offA[0][s][mi]);
                ldsm_x4(al[mi], st + offA[1][s][mi]);
            }
#pragma unroll
            for (int ng = 0; ng < 4; ng++) {
                uint32_t bh[4], bl[4];
                ldsm_x4_t(bh, st + offB[0][s][ng]);
                ldsm_x4_t(bl, st + offB[1][s][ng]);
#pragma unroll
                for (int mi = 0; mi < 2; mi++) {
                    mma_bf16(acc[mi][ng*2],   ah[mi], bh);
                    mma_bf16(acc[mi][ng*2],   ah[mi], bl);
                    mma_bf16(acc[mi][ng*2],   al[mi], bh);
                    mma_bf16(acc[mi][ng*2+1], ah[mi], bh + 2);
                    mma_bf16(acc[mi][ng*2+1], ah[mi], bl + 2);
                    mma_bf16(acc[mi][ng*2+1], al[mi], bh + 2);
                }
            }
        }
        __syncthreads();
    }

    // --- epilogue -----------------------------------------------------------
    // C frag: elem e: row = lane>>2 + 8*(e>>1), col = (lane&3)*2 + (e&1)
    float bias_v[16];
#pragma unroll
    for (int nf = 0; nf < 8; nf++)
#pragma unroll
        for (int ec = 0; ec < 2; ec++)
            bias_v[nf*2 + ec] = __ldg(&bias[col0 + wn*64 + nf*8 + (lane&3)*2 + ec]);

    float invf[8];
    if (mode < 2) {
#pragma unroll
        for (int nf = 0; nf < 4; nf++)
#pragma unroll
            for (int ec = 0; ec < 2; ec++) {
                const int j = nf*8 + (lane&3)*2 + ec;
                invf[nf*2 + ec] = powf(10000.f, -(float)j / 32.f);
            }
    }
    const int h_idx = blockIdx.x * 2 + wn;

#pragma unroll
    for (int mi = 0; mi < 2; mi++) {
#pragma unroll
        for (int er = 0; er < 2; er++) {
            const int m = wm*32 + mi*16 + (lane >> 2) + er*8;
            const int n = row0 + m;
            const int b = n >> 11;
            const int s = n & 2047;
            if (mode < 2) {
                float* dst = out + (((size_t)(b*Hh + h_idx))*Ss + s)*Dd;
#pragma unroll
                for (int nf = 0; nf < 4; nf++)
#pragma unroll
                    for (int ec = 0; ec < 2; ec++) {
                        const int ii = nf*2 + ec;
                        float sn, cs;
                        sincosf((float)s * invf[ii], &sn, &cs);
                        const float x1 = acc[mi][nf][er*2 + ec]   + bias_v[ii];
                        const float x2 = acc[mi][nf+4][er*2 + ec] + bias_v[ii + 8];
                        const int d = nf*8 + (lane&3)*2 + ec;
                        dst[d]      = x1 * cs - x2 * sn;
                        dst[d + 32] = x2 * cs + x1 * sn;
                    }
            } else if (mode == 2) {
                float* dst = out + (((size_t)(b*Hh + h_idx))*Ss + s)*Dd;
#pragma unroll
                for (int nf = 0; nf < 8; nf++)
#pragma unroll
                    for (int ec = 0; ec < 2; ec++) {
                        const int d = nf*8 + (lane&3)*2 + ec;
                        dst[d] = acc[mi][nf][er*2 + ec] + bias_v[nf*2 + ec];
                    }
            } else {
                float* dst = out + (size_t)n * DM + col0 + wn*64;
#pragma unroll
                for (int nf = 0; nf < 8; nf++)
#pragma unroll
                    for (int ec = 0; ec < 2; ec++) {
                        const int d = nf*8 + (lane&3)*2 + ec;
                        dst[d] = acc[mi][nf][er*2 + ec] + bias_v[nf*2 + ec];
                    }
            }
        }
    }
}

// ===========================================================================
// Flash attention (SIMT, unchanged): Q-tile 128, K-tile 64, 256 threads
// ===========================================================================
#define SQT_STRIDE 132
#define SKT_STRIDE 68
#define SV_STRIDE  68
#define SPT_STRIDE 131
#define ATTN_SMEM_FLOATS (64*SQT_STRIDE + 64*SKT_STRIDE + 64*SV_STRIDE + 64*SPT_STRIDE)
#define ATTN_SMEM_BYTES  (ATTN_SMEM_FLOATS * 4)

__global__ __launch_bounds__(256, 2)
void attn_kernel()
{
    extern __shared__ float smf[];
    float* sQt = smf;
    float* sKt = sQt + 64 * SQT_STRIDE;
    float* sV  = sKt + 64 * SKT_STRIDE;
    float* sPt = sV  + 64 * SV_STRIDE;

    const int tid = threadIdx.x;
    const int tx  = tid & 15;
    const int ty  = tid >> 4;
    const int qt  = blockIdx.x;
    const int bh  = blockIdx.y;
    const int b   = bh >> 4;
    const int h   = bh & 15;

    const float* Qg = g_Q + ((size_t)bh * Ss + qt * 128) * Dd;
    const float* Kg = g_K + (size_t)bh * Ss * Dd;
    const float* Vg = g_V + (size_t)bh * Ss * Dd;

    {
        const int qr = tid >> 1;
        const int d0 = (tid & 1) * 32;
#pragma unroll
        for (int v = 0; v < 8; v++) {
            const int d = d0 + v * 4;
            float4 qv = *(const float4*)&Qg[(size_t)qr * Dd + d];
            sQt[(d + 0) * SQT_STRIDE + qr] = qv.x * 0.125f;
            sQt[(d + 1) * SQT_STRIDE + qr] = qv.y * 0.125f;
            sQt[(d + 2) * SQT_STRIDE + qr] = qv.z * 0.125f;
            sQt[(d + 3) * SQT_STRIDE + qr] = qv.w * 0.125f;
        }
    }

    float m_i[8], l_i[8], o_acc[8][4];
#pragma unroll
    for (int i = 0; i < 8; i++) {
        m_i[i] = -1e30f; l_i[i] = 0.f;
#pragma unroll
        for (int j = 0; j < 4; j++) o_acc[i][j] = 0.f;
    }

    const int kr  = tid >> 2;
    const int kd0 = (tid & 3) * 16;

    for (int kt = 0; kt < 32; kt++) {
        __syncthreads();
#pragma unroll
        for (int v = 0; v < 4; v++) {
            const int d = kd0 + v * 4;
            float4 kk = *(const float4*)&Kg[((size_t)(kt * 64 + kr)) * Dd + d];
            sKt[(d + 0) * SKT_STRIDE + kr] = kk.x;
            sKt[(d + 1) * SKT_STRIDE + kr] = kk.y;
            sKt[(d + 2) * SKT_STRIDE + kr] = kk.z;
            sKt[(d + 3) * SKT_STRIDE + kr] = kk.w;
            *(float4*)&sV[kr * SV_STRIDE + d] =
                *(const float4*)&Vg[((size_t)(kt * 64 + kr)) * Dd + d];
        }
        __syncthreads();

        float sacc[8][4];
#pragma unroll
        for (int i = 0; i < 8; i++)
#pragma unroll
            for (int j = 0; j < 4; j++) sacc[i][j] = 0.f;

#pragma unroll 8
        for (int d = 0; d < 64; d++) {
            float qa[8], kb[4];
            *(float4*)&qa[0] = *(float4*)&sQt[d * SQT_STRIDE + ty * 8];
            *(float4*)&qa[4] = *(float4*)&sQt[d * SQT_STRIDE + ty * 8 + 4];
            *(float4*)&kb[0] = *(float4*)&sKt[d * SKT_STRIDE + tx * 4];
#pragma unroll
            for (int i = 0; i < 8; i++)
#pragma unroll
                for (int j = 0; j < 4; j++)
                    sacc[i][j] = fmaf(qa[i], kb[j], sacc[i][j]);
        }

#pragma unroll
        for (int i = 0; i < 8; i++) {
            float rmax = fmaxf(fmaxf(sacc[i][0], sacc[i][1]),
                               fmaxf(sacc[i][2], sacc[i][3]));
            rmax = fmaxf(rmax, __shfl_xor_sync(0xffffffffu, rmax, 8));
            rmax = fmaxf(rmax, __shfl_xor_sync(0xffffffffu, rmax, 4));
            rmax = fmaxf(rmax, __shfl_xor_sync(0xffffffffu, rmax, 2));
            rmax = fmaxf(rmax, __shfl_xor_sync(0xffffffffu, rmax, 1));
            const float m_new = fmaxf(m_i[i], rmax);
            const int r = ty * 8 + i;
            float rs = 0.f;
#pragma unroll
            for (int j = 0; j < 4; j++) {
                float p = __expf(sacc[i][j] - m_new);
                sPt[(tx * 4 + j) * SPT_STRIDE + r] = p;
                rs += p;
            }
            rs += __shfl_xor_sync(0xffffffffu, rs, 8);
            rs += __shfl_xor_sync(0xffffffffu, rs, 4);
            rs += __shfl_xor_sync(0xffffffffu, rs, 2);
            rs += __shfl_xor_sync(0xffffffffu, rs, 1);
            const float sc = __expf(m_i[i] - m_new);
            l_i[i] = l_i[i] * sc + rs;
            m_i[i] = m_new;
#pragma unroll
            for (int j = 0; j < 4; j++) o_acc[i][j] *= sc;
        }
        __syncthreads();

#pragma unroll 8
        for (int k = 0; k < 64; k++) {
            float pa[8], vb[4];
#pragma unroll
            for (int i = 0; i < 8; i++)
                pa[i] = sPt[k * SPT_STRIDE + ty * 8 + i];
            *(float4*)&vb[0] = *(float4*)&sV[k * SV_STRIDE + tx * 4];
#pragma unroll
            for (int i = 0; i < 8; i++)
#pragma unroll
                for (int j = 0; j < 4; j++)
                    o_acc[i][j] = fmaf(pa[i], vb[j], o_acc[i][j]);
        }
    }

#pragma unroll
    for (int i = 0; i < 8; i++) {
        const float inv = 1.f / l_i[i];
        const int srow = qt * 128 + ty * 8 + i;
        float4 v;
        v.x = o_acc[i][0] * inv;
        v.y = o_acc[i][1] * inv;
        v.z = o_acc[i][2] * inv;
        v.w = o_acc[i][3] * inv;
        *(float4*)&g_AO[((size_t)b * Ss + srow) * DM + h * 64 + tx * 4] = v;
    }
}

// ---------------------------------------------------------------------------
extern "C" void kernel_launch(void* const* d_in, const int* in_sizes, int n_in,
                              void* d_out, int out_size)
{
    const float* x  = (const float*)d_in[0];
    const float* wq = (const float*)d_in[1];
    const float* bq = (const float*)d_in[2];
    const float* wk = (const float*)d_in[3];
    const float* bk = (const float*)d_in[4];
    const float* wv = (const float*)d_in[5];
    const float* bv = (const float*)d_in[6];
    const float* wo = (const float*)d_in[7];
    const float* bo = (const float*)d_in[8];
    float* out = (float*)d_out;

    cudaFuncSetAttribute(gemm_bf16split,
                         cudaFuncAttributeMaxDynamicSharedMemorySize, GEMM_SMEM);
    cudaFuncSetAttribute(attn_kernel,
                         cudaFuncAttributeMaxDynamicSharedMemorySize, ATTN_SMEM_BYTES);

    float* gQ;  cudaGetSymbolAddress((void**)&gQ,  g_Q);
    float* gK;  cudaGetSymbolAddress((void**)&gK,  g_K);
    float* gV;  cudaGetSymbolAddress((void**)&gV,  g_V);
    float* gAO; cudaGetSymbolAddress((void**)&gAO, g_AO);
    __nv_bfloat16 *gAhi, *gAlo, *gWhi, *gWlo;
    cudaGetSymbolAddress((void**)&gAhi, g_Ahi);
    cudaGetSymbolAddress((void**)&gAlo, g_Alo);
    cudaGetSymbolAddress((void**)&gWhi, g_Whi);
    cudaGetSymbolAddress((void**)&gWlo, g_Wlo);

    const dim3 gemm_grid(DM / 128, Nn / 128);
    const int NW = DM * DM;      // 1M elems per weight matrix

    // 0) Split inputs into bf16 hi/lo
    split_kernel<<<(Nn*DM/4 + 255)/256, 256>>>(x, gAhi, gAlo, Nn*DM/4);
    split_kernel<<<(NW/4 + 255)/256, 256>>>(wq, gWhi + 0*NW, gWlo + 0*NW, NW/4);
    split_kernel<<<(NW/4 + 255)/256, 256>>>(wk, gWhi + 1*NW, gWlo + 1*NW, NW/4);
    split_kernel<<<(NW/4 + 255)/256, 256>>>(wv, gWhi + 2*NW, gWlo + 2*NW, NW/4);
    split_kernel<<<(NW/4 + 255)/256, 256>>>(wo, gWhi + 3*NW, gWlo + 3*NW, NW/4);

    // 1) Projections (tensor-core mma.sync bf16-split) with fused RoPE for Q/K
    gemm_bf16split<<<gemm_grid, 256, GEMM_SMEM>>>(gAhi, gAlo, gWhi + 0*NW, gWlo + 0*NW, bq, gQ, 0);
    gemm_bf16split<<<gemm_grid, 256, GEMM_SMEM>>>(gAhi, gAlo, gWhi + 1*NW, gWlo + 1*NW, bk, gK, 1);
    gemm_bf16split<<<gemm_grid, 256, GEMM_SMEM>>>(gAhi, gAlo, gWhi + 2*NW, gWlo + 2*NW, bv, gV, 2);
    // 2) Flash attention
    attn_kernel<<<dim3(Ss / 128, BH), 256, ATTN_SMEM_BYTES>>>();
    // 3) Output projection
    split_kernel<<<(Nn*DM/4 + 255)/256, 256>>>(gAO, gAhi, gAlo, Nn*DM/4);
    gemm_bf16split<<<gemm_grid, 256, GEMM_SMEM>>>(gAhi, gAlo, gWhi + 3*NW, gWlo + 3*NW, bo, out, 3);
}

// round 7
// speedup vs baseline: 2.0098x; 1.5278x over previous
#include <cuda_runtime.h>
#include <cuda_bf16.h>
#include <math.h>
#include <stdint.h>

// Problem constants
#define Bb 2
#define Ss 2048
#define DM 1024
#define Hh 16
#define Dd 64
#define Nn (Bb*Ss)          // 4096 tokens
#define BH (Bb*Hh)          // 32

#define QSCALE (0.125f * 1.4426950408889634f)   // 1/sqrt(64) * log2(e)

// Scratch (device globals)
__device__ __nv_bfloat16 g_Ahi[Nn*DM], g_Alo[Nn*DM];          // activations (x, then attn-out)
__device__ __nv_bfloat16 g_Whi[4][DM*DM], g_Wlo[4][DM*DM];    // wq, wk, wv, wo
__device__ __nv_bfloat16 g_Qhi[BH*Ss*Dd], g_Qlo[BH*Ss*Dd];    // [bh][s][d], rope'd + scaled
__device__ __nv_bfloat16 g_Kthi[BH*Ss*Dd], g_Ktlo[BH*Ss*Dd];  // [bh][d][s], rope'd (transposed)
__device__ __nv_bfloat16 g_Vhi[BH*Ss*Dd], g_Vlo[BH*Ss*Dd];    // [bh][s][d]

// ===========================================================================
// PTX helpers
// ===========================================================================
__device__ __forceinline__ uint32_t smem_u32(const void* p) {
    uint32_t a;
    asm("{ .reg .u64 t; cvta.to.shared.u64 t, %1; cvt.u32.u64 %0, t; }"
        : "=r"(a) : "l"(p));
    return a;
}

#define CP_ASYNC16(dst, src) \
    asm volatile("cp.async.cg.shared.global [%0], [%1], 16;" \
                 :: "r"(dst), "l"(src) : "memory")
#define CP_COMMIT() asm volatile("cp.async.commit_group;" ::: "memory")
#define CP_WAIT(n)  asm volatile("cp.async.wait_group %0;" :: "n"(n) : "memory")

__device__ __forceinline__ void ldsm_x4(uint32_t* r, uint32_t addr) {
    asm volatile("ldmatrix.sync.aligned.m8n8.x4.shared.b16 {%0,%1,%2,%3}, [%4];"
                 : "=r"(r[0]), "=r"(r[1]), "=r"(r[2]), "=r"(r[3]) : "r"(addr));
}
__device__ __forceinline__ void ldsm_x4_t(uint32_t* r, uint32_t addr) {
    asm volatile("ldmatrix.sync.aligned.m8n8.x4.trans.shared.b16 {%0,%1,%2,%3}, [%4];"
                 : "=r"(r[0]), "=r"(r[1]), "=r"(r[2]), "=r"(r[3]) : "r"(addr));
}
__device__ __forceinline__ void mma_bf16(float* c, const uint32_t* a,
                                         const uint32_t* b) {
    asm volatile(
        "mma.sync.aligned.m16n8k16.row.col.f32.bf16.bf16.f32 "
        "{%0,%1,%2,%3}, {%4,%5,%6,%7}, {%8,%9}, {%0,%1,%2,%3};"
        : "+f"(c[0]), "+f"(c[1]), "+f"(c[2]), "+f"(c[3])
        : "r"(a[0]), "r"(a[1]), "r"(a[2]), "r"(a[3]), "r"(b[0]), "r"(b[1]));
}
__device__ __forceinline__ float ex2f(float x) {
    float y;
    asm("ex2.approx.ftz.f32 %0, %1;" : "=f"(y) : "f"(x));
    return y;
}
// Split pair (a,b) into packed bf16x2 hi and lo (low half = a)
__device__ __forceinline__ void split2(float a, float b, uint32_t& hp, uint32_t& lp) {
    __nv_bfloat16 ha = __float2bfloat16(a), hb = __float2bfloat16(b);
    float la = a - __bfloat162float(ha);
    float lb = b - __bfloat162float(hb);
    __nv_bfloat162 hv(ha, hb);
    __nv_bfloat162 lv(__float2bfloat16(la), __float2bfloat16(lb));
    hp = *(uint32_t*)&hv;
    lp = *(uint32_t*)&lv;
}

// ===========================================================================
// Split fp32 -> bf16 hi + lo
// ===========================================================================
__global__ void split_kernel(const float* __restrict__ src,
                             __nv_bfloat16* __restrict__ hi,
                             __nv_bfloat16* __restrict__ lo, int n4)
{
    int i = blockIdx.x * blockDim.x + threadIdx.x;
    if (i >= n4) return;
    float4 f = ((const float4*)src)[i];
    __nv_bfloat16 h[4], l[4];
    float v[4] = {f.x, f.y, f.z, f.w};
#pragma unroll
    for (int j = 0; j < 4; j++) {
        h[j] = __float2bfloat16(v[j]);
        l[j] = __float2bfloat16(v[j] - __bfloat162float(h[j]));
    }
    ((uint2*)hi)[i] = *(uint2*)h;
    ((uint2*)lo)[i] = *(uint2*)l;
}

// ===========================================================================
// bf16-split GEMM (mma.sync): 128x128 tile, K-chunk 32, double-buffered.
// mode 0: Q  -> rope, *QSCALE, split, [bh][s][d] bf16 hi/lo
// mode 1: K  -> rope, split, TRANSPOSED [bh][d][s] bf16 hi/lo
// mode 2: V  -> split, [bh][s][d] bf16 hi/lo
// mode 3: O  -> fp32 row-major (final output)
// ===========================================================================
#define GSTAGE 32768
#define GEMM_SMEM (2*GSTAGE)

__global__ __launch_bounds__(256, 1)
void gemm_bf16split(const __nv_bfloat16* __restrict__ Ahi,
                    const __nv_bfloat16* __restrict__ Alo,
                    const __nv_bfloat16* __restrict__ Whi,
                    const __nv_bfloat16* __restrict__ Wlo,
                    const float* __restrict__ bias,
                    float* __restrict__ outf,
                    __nv_bfloat16* __restrict__ outh,
                    __nv_bfloat16* __restrict__ outl,
                    int mode)
{
    extern __shared__ __align__(1024) char sm[];
    const uint32_t sb = smem_u32(sm);
    const int tid  = threadIdx.x;
    const int wid  = tid >> 5;
    const int lane = tid & 31;
    const int wm   = wid >> 1;
    const int wn   = wid & 1;
    const int row0 = blockIdx.y * 128;
    const int col0 = blockIdx.x * 128;

    const int a_r  = tid >> 1;
    const int a_u0 = (tid & 1) * 4;
    const int b_arr = tid >> 7;
    const int b_r   = (tid & 127) >> 2;
    const int b_u0  = (tid & 3) * 4;

    const __nv_bfloat16* a_src_base =
        (a_u0 ? Alo : Ahi) + (size_t)(row0 + a_r) * DM;
    const __nv_bfloat16* b_src_base =
        (b_arr ? Wlo : Whi) + (size_t)b_r * DM + col0;

    uint32_t a_dst[4], b_dst[4];
#pragma unroll
    for (int i = 0; i < 4; i++) {
        const int au = a_u0 + i;
        a_dst[i] = (uint32_t)(a_r * 128 + ((au ^ (a_r & 7)) & 7) * 16);
        const int bu = b_u0 + i;
        b_dst[i] = (uint32_t)(16384 + b_arr * 8192 + b_r * 256
                              + (((bu & 8) | ((bu & 7) ^ (b_r & 7)))) * 16);
    }

    const int q  = lane >> 3;
    const int rr = lane & 7;
    uint32_t offA[2][2][2];
#pragma unroll
    for (int s = 0; s < 2; s++)
#pragma unroll
        for (int mi = 0; mi < 2; mi++) {
            const int arow = wm * 32 + mi * 16 + (q & 1) * 8 + rr;
            const int uh = 2 * s + (q >> 1);
            const int ul = 4 + 2 * s + (q >> 1);
            offA[0][s][mi] = (uint32_t)(arow * 128 + (uh ^ (arow & 7)) * 16);
            offA[1][s][mi] = (uint32_t)(arow * 128 + (ul ^ (arow & 7)) * 16);
        }
    uint32_t offB[2][2][4];
#pragma unroll
    for (int s = 0; s < 2; s++)
#pragma unroll
        for (int ng = 0; ng < 4; ng++) {
            const int krow = 16 * s + (q & 1) * 8 + rr;
            const int u = wn * 8 + ng * 2 + (q >> 1);
            const uint32_t sw = (uint32_t)(((u & 8) | ((u & 7) ^ (krow & 7))) * 16);
            offB[0][s][ng] = (uint32_t)(16384 + krow * 256 + sw);
            offB[1][s][ng] = (uint32_t)(16384 + 8192 + krow * 256 + sw);
        }

    float acc[2][8][4];
#pragma unroll
    for (int mi = 0; mi < 2; mi++)
#pragma unroll
        for (int nf = 0; nf < 8; nf++)
#pragma unroll
            for (int e = 0; e < 4; e++) acc[mi][nf][e] = 0.f;

    {
        const uint32_t st = sb;
#pragma unroll
        for (int i = 0; i < 4; i++) {
            const int au = a_u0 + i;
            CP_ASYNC16(st + a_dst[i], a_src_base + (au & 3) * 8);
            CP_ASYNC16(st + b_dst[i], b_src_base + (b_u0 + i) * 8);
        }
        CP_COMMIT();
    }

    for (int c = 0; c < 32; c++) {
        if (c + 1 < 32) {
            const uint32_t st = sb + ((c + 1) & 1) * GSTAGE;
            const int k0 = (c + 1) * 32;
#pragma unroll
            for (int i = 0; i < 4; i++) {
                const int au = a_u0 + i;
                CP_ASYNC16(st + a_dst[i], a_src_base + k0 + (au & 3) * 8);
                CP_ASYNC16(st + b_dst[i], b_src_base + (size_t)k0 * DM + (b_u0 + i) * 8);
            }
            CP_COMMIT();
            CP_WAIT(1);
        } else {
            CP_WAIT(0);
        }
        __syncthreads();

        const uint32_t st = sb + (c & 1) * GSTAGE;
#pragma unroll
        for (int s = 0; s < 2; s++) {
            uint32_t ah[2][4], al[2][4];
#pragma unroll
            for (int mi = 0; mi < 2; mi++) {
                ldsm_x4(ah[mi], st + offA[0][s][mi]);
                ldsm_x4(al[mi], st + offA[1][s][mi]);
            }
#pragma unroll
            for (int ng = 0; ng < 4; ng++) {
                uint32_t bh4[4], bl4[4];
                ldsm_x4_t(bh4, st + offB[0][s][ng]);
                ldsm_x4_t(bl4, st + offB[1][s][ng]);
#pragma unroll
                for (int mi = 0; mi < 2; mi++) {
                    mma_bf16(acc[mi][ng*2],   ah[mi], bh4);
                    mma_bf16(acc[mi][ng*2],   ah[mi], bl4);
                    mma_bf16(acc[mi][ng*2],   al[mi], bh4);
                    mma_bf16(acc[mi][ng*2+1], ah[mi], bh4 + 2);
                    mma_bf16(acc[mi][ng*2+1], ah[mi], bl4 + 2);
                    mma_bf16(acc[mi][ng*2+1], al[mi], bh4 + 2);
                }
            }
        }
        __syncthreads();
    }

    // --- epilogue ----------------------------------------------------------
    float bias_v[16];
#pragma unroll
    for (int nf = 0; nf < 8; nf++)
#pragma unroll
        for (int ec = 0; ec < 2; ec++)
            bias_v[nf*2 + ec] = __ldg(&bias[col0 + wn*64 + nf*8 + (lane&3)*2 + ec]);

    float invf[8];
    if (mode < 2) {
#pragma unroll
        for (int nf = 0; nf < 4; nf++)
#pragma unroll
            for (int ec = 0; ec < 2; ec++) {
                const int j = nf*8 + (lane&3)*2 + ec;
                invf[nf*2 + ec] = powf(10000.f, -(float)j / 32.f);
            }
    }
    const int h_idx = blockIdx.x * 2 + wn;

#pragma unroll
    for (int mi = 0; mi < 2; mi++) {
#pragma unroll
        for (int er = 0; er < 2; er++) {
            const int m = wm*32 + mi*16 + (lane >> 2) + er*8;
            const int n = row0 + m;
            const int b = n >> 11;
            const int s = n & 2047;
            if (mode < 2) {
                float y1[8], y2[8];
#pragma unroll
                for (int nf = 0; nf < 4; nf++)
#pragma unroll
                    for (int ec = 0; ec < 2; ec++) {
                        const int ii = nf*2 + ec;
                        float sn, cs;
                        sincosf((float)s * invf[ii], &sn, &cs);
                        const float x1 = acc[mi][nf][er*2 + ec]   + bias_v[ii];
                        const float x2 = acc[mi][nf+4][er*2 + ec] + bias_v[ii + 8];
                        y1[ii] = x1 * cs - x2 * sn;
                        y2[ii] = x2 * cs + x1 * sn;
                        if (mode == 0) { y1[ii] *= QSCALE; y2[ii] *= QSCALE; }
                    }
                if (mode == 0) {
                    __nv_bfloat16* dh = outh + (((size_t)(b*Hh + h_idx))*Ss + s)*Dd;
                    __nv_bfloat16* dl = outl + (((size_t)(b*Hh + h_idx))*Ss + s)*Dd;
#pragma unroll
                    for (int nf = 0; nf < 4; nf++) {
                        const int d = nf*8 + (lane&3)*2;
                        uint32_t hp, lp;
                        split2(y1[nf*2], y1[nf*2+1], hp, lp);
                        *(uint32_t*)(dh + d) = hp; *(uint32_t*)(dl + d) = lp;
                        split2(y2[nf*2], y2[nf*2+1], hp, lp);
                        *(uint32_t*)(dh + d + 32) = hp; *(uint32_t*)(dl + d + 32) = lp;
                    }
                } else {
                    // K transposed: [bh][d][s]
                    const size_t base = ((size_t)(b*Hh + h_idx))*Dd;
#pragma unroll
                    for (int nf = 0; nf < 4; nf++)
#pragma unroll
                        for (int ec = 0; ec < 2; ec++) {
                            const int ii = nf*2 + ec;
                            const int d = nf*8 + (lane&3)*2 + ec;
                            __nv_bfloat16 h1 = __float2bfloat16(y1[ii]);
                            __nv_bfloat16 l1 = __float2bfloat16(y1[ii] - __bfloat162float(h1));
                            __nv_bfloat16 h2 = __float2bfloat16(y2[ii]);
                            __nv_bfloat16 l2 = __float2bfloat16(y2[ii] - __bfloat162float(h2));
                            outh[(base + d)*Ss + s]      = h1;
                            outl[(base + d)*Ss + s]      = l1;
                            outh[(base + d + 32)*Ss + s] = h2;
                            outl[(base + d + 32)*Ss + s] = l2;
                        }
                }
            } else if (mode == 2) {
                __nv_bfloat16* dh = outh + (((size_t)(b*Hh + h_idx))*Ss + s)*Dd;
                __nv_bfloat16* dl = outl + (((size_t)(b*Hh + h_idx))*Ss + s)*Dd;
#pragma unroll
                for (int nf = 0; nf < 8; nf++) {
                    const int d = nf*8 + (lane&3)*2;
                    uint32_t hp, lp;
                    split2(acc[mi][nf][er*2] + bias_v[nf*2],
                           acc[mi][nf][er*2+1] + bias_v[nf*2+1], hp, lp);
                    *(uint32_t*)(dh + d) = hp; *(uint32_t*)(dl + d) = lp;
                }
            } else {
                float* dst = outf + (size_t)n * DM + col0 + wn*64;
#pragma unroll
                for (int nf = 0; nf < 8; nf++)
#pragma unroll
                    for (int ec = 0; ec < 2; ec++)
                        dst[nf*8 + (lane&3)*2 + ec] =
                            acc[mi][nf][er*2 + ec] + bias_v[nf*2 + ec];
            }
        }
    }
}

// ===========================================================================
// Flash attention on mma.sync (bf16 hi/lo 3-product for QK^T and P·V)
// CTA: (qt, bh). 128 q-rows, k-tiles of 128, 8 warps (4m x 2n).
// smem: sQhi/lo 32KB | K/V double buffer 2x64KB | stats 1KB  = ~165KB
// ===========================================================================
#define AQ_OFF    0
#define AKV_OFF   32768
#define AKV_SZ    65536
#define ASTAT_OFF 163840
#define ATTN_SMEM (ASTAT_OFF + 2048)

__global__ __launch_bounds__(256, 1)
void attn_mma_kernel()
{
    extern __shared__ __align__(1024) char sm[];
    const uint32_t sb = smem_u32(sm);
    const int tid  = threadIdx.x;
    const int wid  = tid >> 5;
    const int lane = tid & 31;
    const int wm   = wid >> 1;
    const int wn   = wid & 1;
    const int qt   = blockIdx.x;
    const int bh   = blockIdx.y;
    const int b    = bh >> 4;
    const int h    = bh & 15;

    const int q8 = lane >> 3;
    const int rr = lane & 7;

    // cp.async assignments
    const int ca  = tid >> 7;          // 0 = hi array, 1 = lo array
    const int ct  = tid & 127;
    const int kd  = ct >> 1;           // K: d row 0..63
    const int ku0 = (tid & 1) * 8;     // K: unit base
    // global bases
    const __nv_bfloat16* gq = (ca ? g_Qlo : g_Qhi) + ((size_t)bh*Ss + qt*128 + ct)*Dd;
    const __nv_bfloat16* gk = (ca ? g_Ktlo : g_Kthi) + ((size_t)bh*Dd + kd)*Ss;
    const __nv_bfloat16* gv = (ca ? g_Vlo : g_Vhi) + ((size_t)bh*Ss + ct)*Dd;

    // Q smem dst (8 units of this thread's row)
    uint32_t qdst[8], kdst[8], vdst[8];
#pragma unroll
    for (int u = 0; u < 8; u++) {
        qdst[u] = (uint32_t)(AQ_OFF + ca*16384 + ct*128 + ((u ^ (ct & 7))) * 16);
        const int ku = ku0 + u;
        kdst[u] = (uint32_t)(ca*16384 + kd*256 + ((ku ^ ((kd & 7) << 1))) * 16);
        vdst[u] = (uint32_t)(32768 + ca*16384 + ct*128 + ((u ^ (ct & 7))) * 16);
    }

    // ldmatrix offsets
    uint32_t qa_off[2][4];   // [mi][kc], hi; lo = +16384
#pragma unroll
    for (int mi = 0; mi < 2; mi++)
#pragma unroll
        for (int kc = 0; kc < 4; kc++) {
            const int row = wm*32 + mi*16 + (q8 & 1)*8 + rr;
            const int u = kc*2 + (q8 >> 1);
            qa_off[mi][kc] = (uint32_t)(AQ_OFF + row*128 + ((u ^ (row & 7))) * 16);
        }

    // prologue: load Q + tile 0
#pragma unroll
    for (int u = 0; u < 8; u++) CP_ASYNC16(sb + qdst[u], gq + u*8);
#pragma unroll
    for (int u = 0; u < 8; u++) {
        CP_ASYNC16(sb + AKV_OFF + kdst[u], gk + (ku0 + u)*8);
        CP_ASYNC16(sb + AKV_OFF + vdst[u], gv + u*8);
    }
    CP_COMMIT();

    float o_acc[2][8][4];
    float m_i[2][2], l_i[2][2];
#pragma unroll
    for (int mi = 0; mi < 2; mi++) {
#pragma unroll
        for (int er = 0; er < 2; er++) { m_i[mi][er] = -1e30f; l_i[mi][er] = 0.f; }
#pragma unroll
        for (int nf = 0; nf < 8; nf++)
#pragma unroll
            for (int e = 0; e < 4; e++) o_acc[mi][nf][e] = 0.f;
    }

    const uint32_t statm = sb + ASTAT_OFF;          // [wn][128] floats
    const uint32_t stats = sb + ASTAT_OFF + 1024;   // [wn][128] floats
    float* statm_f = (float*)(sm + ASTAT_OFF);
    float* stats_f = (float*)(sm + ASTAT_OFF + 1024);

    for (int nt = 0; nt < 16; nt++) {
        const int buf = nt & 1;
        if (nt + 1 < 16) {
            const uint32_t kb = sb + AKV_OFF + (buf ^ 1) * AKV_SZ;
            const int s0 = (nt + 1) * 128;
#pragma unroll
            for (int u = 0; u < 8; u++) {
                CP_ASYNC16(kb + kdst[u], gk + s0 + (ku0 + u)*8);
                CP_ASYNC16(kb + vdst[u], gv + (size_t)s0*Dd + u*8);
            }
            CP_COMMIT();
            CP_WAIT(1);
        } else {
            CP_WAIT(0);
        }
        __syncthreads();

        const uint32_t kbase = sb + AKV_OFF + buf * AKV_SZ;
        const uint32_t vbase = kbase + 32768;

        // ---- S = Q K^T ----
        float sacc[2][8][4];
#pragma unroll
        for (int mi = 0; mi < 2; mi++)
#pragma unroll
            for (int nf = 0; nf < 8; nf++)
#pragma unroll
                for (int e = 0; e < 4; e++) sacc[mi][nf][e] = 0.f;

#pragma unroll
        for (int kc = 0; kc < 4; kc++) {
            uint32_t ah[2][4], al[2][4];
#pragma unroll
            for (int mi = 0; mi < 2; mi++) {
                ldsm_x4(ah[mi], sb + qa_off[mi][kc]);
                ldsm_x4(al[mi], sb + qa_off[mi][kc] + 16384);
            }
#pragma unroll
            for (int ng = 0; ng < 4; ng++) {
                const int dr = kc*16 + (q8 & 1)*8 + rr;
                const int u  = wn*8 + ng*2 + (q8 >> 1);
                const uint32_t ko = kbase + dr*256 + ((u ^ ((dr & 7) << 1))) * 16;
                uint32_t kh[4], kl[4];
                ldsm_x4_t(kh, ko);
                ldsm_x4_t(kl, ko + 16384);
#pragma unroll
                for (int mi = 0; mi < 2; mi++) {
                    mma_bf16(sacc[mi][ng*2],   ah[mi], kh);
                    mma_bf16(sacc[mi][ng*2],   ah[mi], kl);
                    mma_bf16(sacc[mi][ng*2],   al[mi], kh);
                    mma_bf16(sacc[mi][ng*2+1], ah[mi], kh + 2);
                    mma_bf16(sacc[mi][ng*2+1], ah[mi], kl + 2);
                    mma_bf16(sacc[mi][ng*2+1], al[mi], kh + 2);
                }
            }
        }

        // ---- online softmax (cross-warp over wn pair) ----
        float tmax[2][2];
#pragma unroll
        for (int mi = 0; mi < 2; mi++)
#pragma unroll
            for (int er = 0; er < 2; er++) {
                float mx = -1e30f;
#pragma unroll
                for (int nf = 0; nf < 8; nf++) {
                    mx = fmaxf(mx, sacc[mi][nf][er*2]);
                    mx = fmaxf(mx, sacc[mi][nf][er*2+1]);
                }
                mx = fmaxf(mx, __shfl_xor_sync(0xffffffffu, mx, 1));
                mx = fmaxf(mx, __shfl_xor_sync(0xffffffffu, mx, 2));
                tmax[mi][er] = mx;
            }
        if ((lane & 3) == 0) {
#pragma unroll
            for (int mi = 0; mi < 2; mi++)
#pragma unroll
                for (int er = 0; er < 2; er++)
                    statm_f[wn*128 + wm*32 + mi*16 + (lane>>2) + er*8] = tmax[mi][er];
        }
        __syncthreads();

        float m_new[2][2], sc[2][2];
#pragma unroll
        for (int mi = 0; mi < 2; mi++)
#pragma unroll
            for (int er = 0; er < 2; er++) {
                const int r = wm*32 + mi*16 + (lane>>2) + er*8;
                const float mt = fmaxf(statm_f[r], statm_f[128 + r]);
                m_new[mi][er] = fmaxf(m_i[mi][er], mt);
                sc[mi][er] = ex2f(m_i[mi][er] - m_new[mi][er]);
            }

        float rsum[2][2];
#pragma unroll
        for (int mi = 0; mi < 2; mi++)
#pragma unroll
            for (int er = 0; er < 2; er++) {
                float s = 0.f;
#pragma unroll
                for (int nf = 0; nf < 8; nf++) {
#pragma unroll
                    for (int ec = 0; ec < 2; ec++) {
                        float p = ex2f(sacc[mi][nf][er*2+ec] - m_new[mi][er]);
                        sacc[mi][nf][er*2+ec] = p;
                        s += p;
                    }
                }
                s += __shfl_xor_sync(0xffffffffu, s, 1);
                s += __shfl_xor_sync(0xffffffffu, s, 2);
                rsum[mi][er] = s;
            }
        if ((lane & 3) == 0) {
#pragma unroll
            for (int mi = 0; mi < 2; mi++)
#pragma unroll
                for (int er = 0; er < 2; er++)
                    stats_f[wn*128 + wm*32 + mi*16 + (lane>>2) + er*8] = rsum[mi][er];
        }
        __syncthreads();

#pragma unroll
        for (int mi = 0; mi < 2; mi++)
#pragma unroll
            for (int er = 0; er < 2; er++) {
                const int r = wm*32 + mi*16 + (lane>>2) + er*8;
                l_i[mi][er] = l_i[mi][er] * sc[mi][er] + stats_f[r] + stats_f[128 + r];
                m_i[mi][er] = m_new[mi][er];
#pragma unroll
                for (int nf = 0; nf < 8; nf++) {
                    o_acc[mi][nf][er*2]   *= sc[mi][er];
                    o_acc[mi][nf][er*2+1] *= sc[mi][er];
                }
            }

        // ---- O += P V (P in registers: C-frag -> A-frag) ----
#pragma unroll
        for (int kc = 0; kc < 4; kc++) {
            uint32_t ph[2][4], pl[2][4];
#pragma unroll
            for (int mi = 0; mi < 2; mi++) {
                const float* cE = sacc[mi][2*kc];
                const float* cO = sacc[mi][2*kc+1];
                split2(cE[0], cE[1], ph[mi][0], pl[mi][0]);
                split2(cE[2], cE[3], ph[mi][1], pl[mi][1]);
                split2(cO[0], cO[1], ph[mi][2], pl[mi][2]);
                split2(cO[2], cO[3], ph[mi][3], pl[mi][3]);
            }
#pragma unroll
            for (int ng = 0; ng < 4; ng++) {
                const int vr = wn*64 + kc*16 + (q8 & 1)*8 + rr;
                const int u  = ng*2 + (q8 >> 1);
                const uint32_t vo = vbase + vr*128 + ((u ^ (vr & 7))) * 16;
                uint32_t vh[4], vl[4];
                ldsm_x4_t(vh, vo);
                ldsm_x4_t(vl, vo + 16384);
#pragma unroll
                for (int mi = 0; mi < 2; mi++) {
                    mma_bf16(o_acc[mi][ng*2],   ph[mi], vh);
                    mma_bf16(o_acc[mi][ng*2],   pl[mi], vh);
                    mma_bf16(o_acc[mi][ng*2],   ph[mi], vl);
                    mma_bf16(o_acc[mi][ng*2+1], ph[mi], vh + 2);
                    mma_bf16(o_acc[mi][ng*2+1], pl[mi], vh + 2);
                    mma_bf16(o_acc[mi][ng*2+1], ph[mi], vl + 2);
                }
            }
        }
        __syncthreads();
    }

    // ---- epilogue: combine wn partners, normalize, write bf16 hi/lo ----
    float* ex = (float*)sm;   // reuse Q area: [128 rows][64 cols] fp32
    if (wn == 1) {
#pragma unroll
        for (int mi = 0; mi < 2; mi++)
#pragma unroll
            for (int er = 0; er < 2; er++) {
                const int r = wm*32 + mi*16 + (lane>>2) + er*8;
#pragma unroll
                for (int nf = 0; nf < 8; nf++) {
                    const int col = nf*8 + (lane&3)*2;
                    ex[r*64 + col]     = o_acc[mi][nf][er*2];
                    ex[r*64 + col + 1] = o_acc[mi][nf][er*2+1];
                }
            }
    }
    __syncthreads();
    if (wn == 0) {
#pragma unroll
        for (int mi = 0; mi < 2; mi++)
#pragma unroll
            for (int er = 0; er < 2; er++) {
                const int r = wm*32 + mi*16 + (lane>>2) + er*8;
                const float inv = 1.f / l_i[mi][er];
                const size_t nrow = (size_t)(b*Ss + qt*128 + r) * DM + h*64;
#pragma unroll
                for (int nf = 0; nf < 8; nf++) {
                    const int col = nf*8 + (lane&3)*2;
                    const float v0 = (o_acc[mi][nf][er*2]   + ex[r*64 + col])     * inv;
                    const float v1 = (o_acc[mi][nf][er*2+1] + ex[r*64 + col + 1]) * inv;
                    uint32_t hp, lp;
                    split2(v0, v1, hp, lp);
                    *(uint32_t*)(g_Ahi + nrow + col) = hp;
                    *(uint32_t*)(g_Alo + nrow + col) = lp;
                }
            }
    }
}

// ---------------------------------------------------------------------------
extern "C" void kernel_launch(void* const* d_in, const int* in_sizes, int n_in,
                              void* d_out, int out_size)
{
    const float* x  = (const float*)d_in[0];
    const float* wq = (const float*)d_in[1];
    const float* bq = (const float*)d_in[2];
    const float* wk = (const float*)d_in[3];
    const float* bk = (const float*)d_in[4];
    const float* wv = (const float*)d_in[5];
    const float* bv = (const float*)d_in[6];
    const float* wo = (const float*)d_in[7];
    const float* bo = (const float*)d_in[8];
    float* out = (float*)d_out;

    cudaFuncSetAttribute(gemm_bf16split,
                         cudaFuncAttributeMaxDynamicSharedMemorySize, GEMM_SMEM);
    cudaFuncSetAttribute(attn_mma_kernel,
                         cudaFuncAttributeMaxDynamicSharedMemorySize, ATTN_SMEM);

    __nv_bfloat16 *gAhi, *gAlo, *gWhi, *gWlo;
    __nv_bfloat16 *gQh, *gQl, *gKh, *gKl, *gVh, *gVl;
    cudaGetSymbolAddress((void**)&gAhi, g_Ahi);
    cudaGetSymbolAddress((void**)&gAlo, g_Alo);
    cudaGetSymbolAddress((void**)&gWhi, g_Whi);
    cudaGetSymbolAddress((void**)&gWlo, g_Wlo);
    cudaGetSymbolAddress((void**)&gQh, g_Qhi);
    cudaGetSymbolAddress((void**)&gQl, g_Qlo);
    cudaGetSymbolAddress((void**)&gKh, g_Kthi);
    cudaGetSymbolAddress((void**)&gKl, g_Ktlo);
    cudaGetSymbolAddress((void**)&gVh, g_Vhi);
    cudaGetSymbolAddress((void**)&gVl, g_Vlo);

    const dim3 gemm_grid(DM / 128, Nn / 128);
    const int NW = DM * DM;

    // 0) Split inputs into bf16 hi/lo
    split_kernel<<<(Nn*DM/4 + 255)/256, 256>>>(x, gAhi, gAlo, Nn*DM/4);
    split_kernel<<<(NW/4 + 255)/256, 256>>>(wq, gWhi + 0*NW, gWlo + 0*NW, NW/4);
    split_kernel<<<(NW/4 + 255)/256, 256>>>(wk, gWhi + 1*NW, gWlo + 1*NW, NW/4);
    split_kernel<<<(NW/4 + 255)/256, 256>>>(wv, gWhi + 2*NW, gWlo + 2*NW, NW/4);
    split_kernel<<<(NW/4 + 255)/256, 256>>>(wo, gWhi + 3*NW, gWlo + 3*NW, NW/4);

    // 1) Projections: Q (rope+scale), K (rope, transposed), V — all bf16 hi/lo
    gemm_bf16split<<<gemm_grid, 256, GEMM_SMEM>>>(gAhi, gAlo, gWhi + 0*NW, gWlo + 0*NW, bq, nullptr, gQh, gQl, 0);
    gemm_bf16split<<<gemm_grid, 256, GEMM_SMEM>>>(gAhi, gAlo, gWhi + 1*NW, gWlo + 1*NW, bk, nullptr, gKh, gKl, 1);
    gemm_bf16split<<<gemm_grid, 256, GEMM_SMEM>>>(gAhi, gAlo, gWhi + 2*NW, gWlo + 2*NW, bv, nullptr, gVh, gVl, 2);
    // 2) Flash attention on tensor cores (writes g_Ahi/g_Alo)
    attn_mma_kernel<<<dim3(Ss / 128, BH), 256, ATTN_SMEM>>>();
    // 3) Output projection (fp32 out)
    gemm_bf16split<<<gemm_grid, 256, GEMM_SMEM>>>(gAhi, gAlo, gWhi + 3*NW, gWlo + 3*NW, bo, out, nullptr, nullptr, 3);
}

// round 9
// speedup vs baseline: 2.0496x; 1.0198x over previous
#include <cuda_runtime.h>
#include <cuda_bf16.h>
#include <math.h>
#include <stdint.h>

// Problem constants
#define Bb 2
#define Ss 2048
#define DM 1024
#define Hh 16
#define Dd 64
#define Nn (Bb*Ss)          // 4096 tokens
#define BH (Bb*Hh)          // 32

#define QSCALE (0.125f * 1.4426950408889634f)   // 1/sqrt(64) * log2(e)

// Scratch (device globals)
__device__ __nv_bfloat16 g_Ahi[Nn*DM], g_Alo[Nn*DM];          // activations (x, then attn-out)
__device__ __nv_bfloat16 g_Whi[4][DM*DM], g_Wlo[4][DM*DM];    // wq, wk, wv, wo
__device__ __nv_bfloat16 g_Qhi[BH*Ss*Dd], g_Qlo[BH*Ss*Dd];    // [bh][s][d], rope'd + scaled
__device__ __nv_bfloat16 g_Kthi[BH*Ss*Dd], g_Ktlo[BH*Ss*Dd];  // [bh][d][s], rope'd (transposed)
__device__ __nv_bfloat16 g_Vhi[BH*Ss*Dd], g_Vlo[BH*Ss*Dd];    // [bh][s][d]

// ===========================================================================
// PTX helpers
// ===========================================================================
__device__ __forceinline__ uint32_t smem_u32(const void* p) {
    uint32_t a;
    asm("{ .reg .u64 t; cvta.to.shared.u64 t, %1; cvt.u32.u64 %0, t; }"
        : "=r"(a) : "l"(p));
    return a;
}

#define CP_ASYNC16(dst, src) \
    asm volatile("cp.async.cg.shared.global [%0], [%1], 16;" \
                 :: "r"(dst), "l"(src) : "memory")
#define CP_COMMIT() asm volatile("cp.async.commit_group;" ::: "memory")
#define CP_WAIT(n)  asm volatile("cp.async.wait_group %0;" :: "n"(n) : "memory")

__device__ __forceinline__ void ldsm_x4(uint32_t* r, uint32_t addr) {
    asm volatile("ldmatrix.sync.aligned.m8n8.x4.shared.b16 {%0,%1,%2,%3}, [%4];"
                 : "=r"(r[0]), "=r"(r[1]), "=r"(r[2]), "=r"(r[3]) : "r"(addr));
}
__device__ __forceinline__ void ldsm_x4_t(uint32_t* r, uint32_t addr) {
    asm volatile("ldmatrix.sync.aligned.m8n8.x4.trans.shared.b16 {%0,%1,%2,%3}, [%4];"
                 : "=r"(r[0]), "=r"(r[1]), "=r"(r[2]), "=r"(r[3]) : "r"(addr));
}
__device__ __forceinline__ void mma_bf16(float* c, const uint32_t* a,
                                         const uint32_t* b) {
    asm volatile(
        "mma.sync.aligned.m16n8k16.row.col.f32.bf16.bf16.f32 "
        "{%0,%1,%2,%3}, {%4,%5,%6,%7}, {%8,%9}, {%0,%1,%2,%3};"
        : "+f"(c[0]), "+f"(c[1]), "+f"(c[2]), "+f"(c[3])
        : "r"(a[0]), "r"(a[1]), "r"(a[2]), "r"(a[3]), "r"(b[0]), "r"(b[1]));
}
__device__ __forceinline__ float ex2f(float x) {
    float y;
    asm("ex2.approx.ftz.f32 %0, %1;" : "=f"(y) : "f"(x));
    return y;
}
// Split pair (a,b) into packed bf16x2 hi and lo (low half = a)
__device__ __forceinline__ void split2(float a, float b, uint32_t& hp, uint32_t& lp) {
    __nv_bfloat16 ha = __float2bfloat16(a), hb = __float2bfloat16(b);
    float la = a - __bfloat162float(ha);
    float lb = b - __bfloat162float(hb);
    __nv_bfloat162 hv(ha, hb);
    __nv_bfloat162 lv(__float2bfloat16(la), __float2bfloat16(lb));
    hp = *(uint32_t*)&hv;
    lp = *(uint32_t*)&lv;
}

// ===========================================================================
// Split fp32 -> bf16 hi + lo
// ===========================================================================
__global__ void split_kernel(const float* __restrict__ src,
                             __nv_bfloat16* __restrict__ hi,
                             __nv_bfloat16* __restrict__ lo, int n4)
{
    int i = blockIdx.x * blockDim.x + threadIdx.x;
    if (i >= n4) return;
    float4 f = ((const float4*)src)[i];
    __nv_bfloat16 h[4], l[4];
    float v[4] = {f.x, f.y, f.z, f.w};
#pragma unroll
    for (int j = 0; j < 4; j++) {
        h[j] = __float2bfloat16(v[j]);
        l[j] = __float2bfloat16(v[j] - __bfloat162float(h[j]));
    }
    ((uint2*)hi)[i] = *(uint2*)h;
    ((uint2*)lo)[i] = *(uint2*)l;
}

// ===========================================================================
// bf16-split GEMM (mma.sync): 128x128 tile, K-chunk 32, double-buffered.
// mode 0: Q  -> rope, *QSCALE, split, [bh][s][d] bf16 hi/lo
// mode 1: K  -> rope, split, TRANSPOSED [bh][d][s] bf16 hi/lo
// mode 2: V  -> split, [bh][s][d] bf16 hi/lo
// mode 3: O  -> fp32 row-major (final output)
// mode_sel < 0: mode = blockIdx.z (fused QKV launch)
// ===========================================================================
#define GSTAGE 32768
#define GEMM_SMEM (2*GSTAGE)

struct GArgs {
    const __nv_bfloat16 *Ahi, *Alo, *Wh, *Wl;   // Wh/Wl: base of 4 matrices
    const float *b0, *b1, *b2, *b3;
    float *outf;
    __nv_bfloat16 *q_h, *q_l, *kt_h, *kt_l, *v_h, *v_l;
    int mode_sel;
};

__global__ __launch_bounds__(256, 1)
void gemm_bf16split(GArgs a)
{
    extern __shared__ __align__(1024) char sm[];
    const uint32_t sb = smem_u32(sm);
    const int mode = (a.mode_sel < 0) ? (int)blockIdx.z : a.mode_sel;

    const __nv_bfloat16* Ahi = a.Ahi;
    const __nv_bfloat16* Alo = a.Alo;
    const __nv_bfloat16* Whi = a.Wh + (size_t)mode * DM * DM;
    const __nv_bfloat16* Wlo = a.Wl + (size_t)mode * DM * DM;
    const float* bias = (mode == 0) ? a.b0 : (mode == 1) ? a.b1
                       : (mode == 2) ? a.b2 : a.b3;
    __nv_bfloat16* outh = (mode == 0) ? a.q_h : (mode == 1) ? a.kt_h : a.v_h;
    __nv_bfloat16* outl = (mode == 0) ? a.q_l : (mode == 1) ? a.kt_l : a.v_l;

    const int tid  = threadIdx.x;
    const int wid  = tid >> 5;
    const int lane = tid & 31;
    const int wm   = wid >> 1;
    const int wn   = wid & 1;
    const int row0 = blockIdx.y * 128;
    const int col0 = blockIdx.x * 128;

    const int a_r  = tid >> 1;
    const int a_u0 = (tid & 1) * 4;
    const int b_arr = tid >> 7;
    const int b_r   = (tid & 127) >> 2;
    const int b_u0  = (tid & 3) * 4;

    const __nv_bfloat16* a_src_base =
        (a_u0 ? Alo : Ahi) + (size_t)(row0 + a_r) * DM;
    const __nv_bfloat16* b_src_base =
        (b_arr ? Wlo : Whi) + (size_t)b_r * DM + col0;

    uint32_t a_dst[4], b_dst[4];
#pragma unroll
    for (int i = 0; i < 4; i++) {
        const int au = a_u0 + i;
        a_dst[i] = (uint32_t)(a_r * 128 + ((au ^ (a_r & 7)) & 7) * 16);
        const int bu = b_u0 + i;
        b_dst[i] = (uint32_t)(16384 + b_arr * 8192 + b_r * 256
                              + (((bu & 8) | ((bu & 7) ^ (b_r & 7)))) * 16);
    }

    const int q  = lane >> 3;
    const int rr = lane & 7;
    uint32_t offA[2][2][2];
#pragma unroll
    for (int s = 0; s < 2; s++)
#pragma unroll
        for (int mi = 0; mi < 2; mi++) {
            const int arow = wm * 32 + mi * 16 + (q & 1) * 8 + rr;
            const int uh = 2 * s + (q >> 1);
            const int ul = 4 + 2 * s + (q >> 1);
            offA[0][s][mi] = (uint32_t)(arow * 128 + (uh ^ (arow & 7)) * 16);
            offA[1][s][mi] = (uint32_t)(arow * 128 + (ul ^ (arow & 7)) * 16);
        }
    uint32_t offB[2][2][4];
#pragma unroll
    for (int s = 0; s < 2; s++)
#pragma unroll
        for (int ng = 0; ng < 4; ng++) {
            const int krow = 16 * s + (q & 1) * 8 + rr;
            const int u = wn * 8 + ng * 2 + (q >> 1);
            const uint32_t sw = (uint32_t)(((u & 8) | ((u & 7) ^ (krow & 7))) * 16);
            offB[0][s][ng] = (uint32_t)(16384 + krow * 256 + sw);
            offB[1][s][ng] = (uint32_t)(16384 + 8192 + krow * 256 + sw);
        }

    float acc[2][8][4];
#pragma unroll
    for (int mi = 0; mi < 2; mi++)
#pragma unroll
        for (int nf = 0; nf < 8; nf++)
#pragma unroll
            for (int e = 0; e < 4; e++) acc[mi][nf][e] = 0.f;

    {
        const uint32_t st = sb;
#pragma unroll
        for (int i = 0; i < 4; i++) {
            const int au = a_u0 + i;
            CP_ASYNC16(st + a_dst[i], a_src_base + (au & 3) * 8);
            CP_ASYNC16(st + b_dst[i], b_src_base + (b_u0 + i) * 8);
        }
        CP_COMMIT();
    }

    for (int c = 0; c < 32; c++) {
        if (c + 1 < 32) {
            const uint32_t st = sb + ((c + 1) & 1) * GSTAGE;
            const int k0 = (c + 1) * 32;
#pragma unroll
            for (int i = 0; i < 4; i++) {
                const int au = a_u0 + i;
                CP_ASYNC16(st + a_dst[i], a_src_base + k0 + (au & 3) * 8);
                CP_ASYNC16(st + b_dst[i], b_src_base + (size_t)k0 * DM + (b_u0 + i) * 8);
            }
            CP_COMMIT();
            CP_WAIT(1);
        } else {
            CP_WAIT(0);
        }
        __syncthreads();

        const uint32_t st = sb + (c & 1) * GSTAGE;
#pragma unroll
        for (int s = 0; s < 2; s++) {
            uint32_t ah[2][4], al[2][4];
#pragma unroll
            for (int mi = 0; mi < 2; mi++) {
                ldsm_x4(ah[mi], st + offA[0][s][mi]);
                ldsm_x4(al[mi], st + offA[1][s][mi]);
            }
#pragma unroll
            for (int ng = 0; ng < 4; ng++) {
                uint32_t bh4[4], bl4[4];
                ldsm_x4_t(bh4, st + offB[0][s][ng]);
                ldsm_x4_t(bl4, st + offB[1][s][ng]);
#pragma unroll
                for (int mi = 0; mi < 2; mi++) {
                    mma_bf16(acc[mi][ng*2],   ah[mi], bh4);
                    mma_bf16(acc[mi][ng*2],   ah[mi], bl4);
                    mma_bf16(acc[mi][ng*2],   al[mi], bh4);
                    mma_bf16(acc[mi][ng*2+1], ah[mi], bh4 + 2);
                    mma_bf16(acc[mi][ng*2+1], ah[mi], bl4 + 2);
                    mma_bf16(acc[mi][ng*2+1], al[mi], bh4 + 2);
                }
            }
        }
        __syncthreads();
    }

    // --- epilogue ----------------------------------------------------------
    float bias_v[16];
#pragma unroll
    for (int nf = 0; nf < 8; nf++)
#pragma unroll
        for (int ec = 0; ec < 2; ec++)
            bias_v[nf*2 + ec] = __ldg(&bias[col0 + wn*64 + nf*8 + (lane&3)*2 + ec]);

    float invf[8];
    if (mode < 2) {
#pragma unroll
        for (int nf = 0; nf < 4; nf++)
#pragma unroll
            for (int ec = 0; ec < 2; ec++) {
                const int j = nf*8 + (lane&3)*2 + ec;
                invf[nf*2 + ec] = powf(10000.f, -(float)j / 32.f);
            }
    }
    const int h_idx = blockIdx.x * 2 + wn;

#pragma unroll
    for (int mi = 0; mi < 2; mi++) {
#pragma unroll
        for (int er = 0; er < 2; er++) {
            const int m = wm*32 + mi*16 + (lane >> 2) + er*8;
            const int n = row0 + m;
            const int b = n >> 11;
            const int s = n & 2047;
            if (mode < 2) {
                float y1[8], y2[8];
#pragma unroll
                for (int nf = 0; nf < 4; nf++)
#pragma unroll
                    for (int ec = 0; ec < 2; ec++) {
                        const int ii = nf*2 + ec;
                        float sn, cs;
                        sincosf((float)s * invf[ii], &sn, &cs);
                        const float x1 = acc[mi][nf][er*2 + ec]   + bias_v[ii];
                        const float x2 = acc[mi][nf+4][er*2 + ec] + bias_v[ii + 8];
                        y1[ii] = x1 * cs - x2 * sn;
                        y2[ii] = x2 * cs + x1 * sn;
                        if (mode == 0) { y1[ii] *= QSCALE; y2[ii] *= QSCALE; }
                    }
                if (mode == 0) {
                    __nv_bfloat16* dh = outh + (((size_t)(b*Hh + h_idx))*Ss + s)*Dd;
                    __nv_bfloat16* dl = outl + (((size_t)(b*Hh + h_idx))*Ss + s)*Dd;
#pragma unroll
                    for (int nf = 0; nf < 4; nf++) {
                        const int d = nf*8 + (lane&3)*2;
                        uint32_t hp, lp;
                        split2(y1[nf*2], y1[nf*2+1], hp, lp);
                        *(uint32_t*)(dh + d) = hp; *(uint32_t*)(dl + d) = lp;
                        split2(y2[nf*2], y2[nf*2+1], hp, lp);
                        *(uint32_t*)(dh + d + 32) = hp; *(uint32_t*)(dl + d + 32) = lp;
                    }
                } else {
                    // K transposed: [bh][d][s]
                    const size_t base = ((size_t)(b*Hh + h_idx))*Dd;
#pragma unroll
                    for (int nf = 0; nf < 4; nf++)
#pragma unroll
                        for (int ec = 0; ec < 2; ec++) {
                            const int ii = nf*2 + ec;
                            const int d = nf*8 + (lane&3)*2 + ec;
                            __nv_bfloat16 h1 = __float2bfloat16(y1[ii]);
                            __nv_bfloat16 l1 = __float2bfloat16(y1[ii] - __bfloat162float(h1));
                            __nv_bfloat16 h2 = __float2bfloat16(y2[ii]);
                            __nv_bfloat16 l2 = __float2bfloat16(y2[ii] - __bfloat162float(h2));
                            outh[(base + d)*Ss + s]      = h1;
                            outl[(base + d)*Ss + s]      = l1;
                            outh[(base + d + 32)*Ss + s] = h2;
                            outl[(base + d + 32)*Ss + s] = l2;
                        }
                }
            } else if (mode == 2) {
                __nv_bfloat16* dh = outh + (((size_t)(b*Hh + h_idx))*Ss + s)*Dd;
                __nv_bfloat16* dl = outl + (((size_t)(b*Hh + h_idx))*Ss + s)*Dd;
#pragma unroll
                for (int nf = 0; nf < 8; nf++) {
                    const int d = nf*8 + (lane&3)*2;
                    uint32_t hp, lp;
                    split2(acc[mi][nf][er*2] + bias_v[nf*2],
                           acc[mi][nf][er*2+1] + bias_v[nf*2+1], hp, lp);
                    *(uint32_t*)(dh + d) = hp; *(uint32_t*)(dl + d) = lp;
                }
            } else {
                float* dst = a.outf + (size_t)n * DM + col0 + wn*64;
#pragma unroll
                for (int nf = 0; nf < 8; nf++)
#pragma unroll
                    for (int ec = 0; ec < 2; ec++)
                        dst[nf*8 + (lane&3)*2 + ec] =
                            acc[mi][nf][er*2 + ec] + bias_v[nf*2 + ec];
            }
        }
    }
}

// ===========================================================================
// Flash attention on mma.sync, FA2-style warp-row ownership.
// CTA: (qt, bh). 128 q-rows, k-tiles of 128, 8 warps; warp w owns rows
// w*16..w*16+15 across ALL 128 key columns -> softmax fully in-register.
// Q hi/lo fragments cached in registers across all tiles.
// smem: Q 32KB | K/V double buffer 2x64KB = 160KB
// ===========================================================================
#define AQ_OFF    0
#define AKV_OFF   32768
#define AKV_SZ    65536
#define ATTN_SMEM (AKV_OFF + 2*AKV_SZ)

__global__ __launch_bounds__(256, 1)
void attn_mma_kernel()
{
    extern __shared__ __align__(1024) char sm[];
    const uint32_t sb = smem_u32(sm);
    const int tid  = threadIdx.x;
    const int wid  = tid >> 5;
    const int lane = tid & 31;
    const int qt   = blockIdx.x;
    const int bh   = blockIdx.y;
    const int b    = bh >> 4;
    const int h    = bh & 15;

    const int q8 = lane >> 3;
    const int rr = lane & 7;

    // cp.async assignments
    const int ca  = tid >> 7;          // 0 = hi array, 1 = lo array
    const int ct  = tid & 127;
    const int kd  = ct >> 1;           // K: d row 0..63
    const int ku0 = (tid & 1) * 8;     // K: unit base
    const __nv_bfloat16* gq = (ca ? g_Qlo : g_Qhi) + ((size_t)bh*Ss + qt*128 + ct)*Dd;
    const __nv_bfloat16* gk = (ca ? g_Ktlo : g_Kthi) + ((size_t)bh*Dd + kd)*Ss;
    const __nv_bfloat16* gv = (ca ? g_Vlo : g_Vhi) + ((size_t)bh*Ss + ct)*Dd;

    uint32_t qdst[8], kdst[8], vdst[8];
#pragma unroll
    for (int u = 0; u < 8; u++) {
        qdst[u] = (uint32_t)(AQ_OFF + ca*16384 + ct*128 + ((u ^ (ct & 7))) * 16);
        const int ku = ku0 + u;
        kdst[u] = (uint32_t)(ca*16384 + kd*256 + ((ku ^ ((kd & 7) << 1))) * 16);
        vdst[u] = (uint32_t)(32768 + ca*16384 + ct*128 + ((u ^ (ct & 7))) * 16);
    }

    // Q fragment ldmatrix offsets (warp rows wid*16..+15)
    uint32_t qa_off[4];
#pragma unroll
    for (int kc = 0; kc < 4; kc++) {
        const int row = wid*16 + (q8 & 1)*8 + rr;
        const int u = kc*2 + (q8 >> 1);
        qa_off[kc] = (uint32_t)(AQ_OFF + row*128 + ((u ^ (row & 7))) * 16);
    }

    // prologue: load Q + tile 0
#pragma unroll
    for (int u = 0; u < 8; u++) CP_ASYNC16(sb + qdst[u], gq + u*8);
#pragma unroll
    for (int u = 0; u < 8; u++) {
        CP_ASYNC16(sb + AKV_OFF + kdst[u], gk + (ku0 + u)*8);
        CP_ASYNC16(sb + AKV_OFF + vdst[u], gv + u*8);
    }
    CP_COMMIT();

    uint32_t qh_f[4][4], ql_f[4][4];     // Q frags cached across tiles
    float o_acc[8][4];
    float m_i[2], l_i[2];
#pragma unroll
    for (int er = 0; er < 2; er++) { m_i[er] = -1e30f; l_i[er] = 0.f; }
#pragma unroll
    for (int nf = 0; nf < 8; nf++)
#pragma unroll
        for (int e = 0; e < 4; e++) o_acc[nf][e] = 0.f;

    for (int nt = 0; nt < 16; nt++) {
        const int buf = nt & 1;
        if (nt + 1 < 16) {
            const uint32_t kb = sb + AKV_OFF + (buf ^ 1) * AKV_SZ;
            const int s0 = (nt + 1) * 128;
#pragma unroll
            for (int u = 0; u < 8; u++) {
                CP_ASYNC16(kb + kdst[u], gk + s0 + (ku0 + u)*8);
                CP_ASYNC16(kb + vdst[u], gv + (size_t)s0*Dd + u*8);
            }
            CP_COMMIT();
            CP_WAIT(1);
        } else {
            CP_WAIT(0);
        }
        __syncthreads();

        if (nt == 0) {
#pragma unroll
            for (int kc = 0; kc < 4; kc++) {
                ldsm_x4(qh_f[kc], sb + qa_off[kc]);
                ldsm_x4(ql_f[kc], sb + qa_off[kc] + 16384);
            }
        }

        const uint32_t kbase = sb + AKV_OFF + buf * AKV_SZ;
        const uint32_t vbase = kbase + 32768;

        // ---- S = Q K^T  (16 rows x 128 cols per warp) ----
        float sacc[16][4];
#pragma unroll
        for (int nf = 0; nf < 16; nf++)
#pragma unroll
            for (int e = 0; e < 4; e++) sacc[nf][e] = 0.f;

#pragma unroll
        for (int kc = 0; kc < 4; kc++) {
#pragma unroll
            for (int ng = 0; ng < 8; ng++) {
                const int dr = kc*16 + (q8 & 1)*8 + rr;
                const int u  = ng*2 + (q8 >> 1);
                const uint32_t ko = kbase + dr*256 + ((u ^ ((dr & 7) << 1))) * 16;
                uint32_t kh[4], kl[4];
                ldsm_x4_t(kh, ko);
                ldsm_x4_t(kl, ko + 16384);
                mma_bf16(sacc[ng*2],   qh_f[kc], kh);
                mma_bf16(sacc[ng*2],   qh_f[kc], kl);
                mma_bf16(sacc[ng*2],   ql_f[kc], kh);
                mma_bf16(sacc[ng*2+1], qh_f[kc], kh + 2);
                mma_bf16(sacc[ng*2+1], qh_f[kc], kl + 2);
                mma_bf16(sacc[ng*2+1], ql_f[kc], kh + 2);
            }
        }

        // ---- online softmax (fully in-register, quad shfl) ----
        float m_new[2], sc[2];
#pragma unroll
        for (int er = 0; er < 2; er++) {
            float mx = -1e30f;
#pragma unroll
            for (int nf = 0; nf < 16; nf++) {
                mx = fmaxf(mx, sacc[nf][er*2]);
                mx = fmaxf(mx, sacc[nf][er*2+1]);
            }
            mx = fmaxf(mx, __shfl_xor_sync(0xffffffffu, mx, 1));
            mx = fmaxf(mx, __shfl_xor_sync(0xffffffffu, mx, 2));
            m_new[er] = fmaxf(m_i[er], mx);
            sc[er] = ex2f(m_i[er] - m_new[er]);
        }
#pragma unroll
        for (int er = 0; er < 2; er++) {
            float rs = 0.f;
#pragma unroll
            for (int nf = 0; nf < 16; nf++) {
#pragma unroll
                for (int ec = 0; ec < 2; ec++) {
                    float p = ex2f(sacc[nf][er*2+ec] - m_new[er]);
                    sacc[nf][er*2+ec] = p;
                    rs += p;
                }
            }
            rs += __shfl_xor_sync(0xffffffffu, rs, 1);
            rs += __shfl_xor_sync(0xffffffffu, rs, 2);
            l_i[er] = l_i[er] * sc[er] + rs;
            m_i[er] = m_new[er];
#pragma unroll
            for (int nf = 0; nf < 8; nf++) {
                o_acc[nf][er*2]   *= sc[er];
                o_acc[nf][er*2+1] *= sc[er];
            }
        }

        // ---- O += P V (P in registers: C-frag -> A-frag) ----
#pragma unroll
        for (int kc = 0; kc < 8; kc++) {
            uint32_t ph[4], pl[4];
            const float* cE = sacc[2*kc];
            const float* cO = sacc[2*kc+1];
            split2(cE[0], cE[1], ph[0], pl[0]);
            split2(cE[2], cE[3], ph[1], pl[1]);
            split2(cO[0], cO[1], ph[2], pl[2]);
            split2(cO[2], cO[3], ph[3], pl[3]);
#pragma unroll
            for (int ng = 0; ng < 4; ng++) {
                const int vr = kc*16 + (q8 & 1)*8 + rr;
                const int u  = ng*2 + (q8 >> 1);
                const uint32_t vo = vbase + vr*128 + ((u ^ (vr & 7))) * 16;
                uint32_t vh[4], vl[4];
                ldsm_x4_t(vh, vo);
                ldsm_x4_t(vl, vo + 16384);
                mma_bf16(o_acc[ng*2],   ph, vh);
                mma_bf16(o_acc[ng*2],   pl, vh);
                mma_bf16(o_acc[ng*2],   ph, vl);
                mma_bf16(o_acc[ng*2+1], ph, vh + 2);
                mma_bf16(o_acc[ng*2+1], pl, vh + 2);
                mma_bf16(o_acc[ng*2+1], ph, vl + 2);
            }
        }
        __syncthreads();
    }

    // ---- epilogue: per-warp direct write (no cross-warp combine) ----
#pragma unroll
    for (int er = 0; er < 2; er++) {
        const int r = wid*16 + (lane >> 2) + er*8;
        const float inv = 1.f / l_i[er];
        const size_t nrow = (size_t)(b*Ss + qt*128 + r) * DM + h*64;
#pragma unroll
        for (int nf = 0; nf < 8; nf++) {
            const int col = nf*8 + (lane & 3)*2;
            const float v0 = o_acc[nf][er*2]   * inv;
            const float v1 = o_acc[nf][er*2+1] * inv;
            uint32_t hp, lp;
            split2(v0, v1, hp, lp);
            *(uint32_t*)(g_Ahi + nrow + col) = hp;
            *(uint32_t*)(g_Alo + nrow + col) = lp;
        }
    }
}

// ---------------------------------------------------------------------------
extern "C" void kernel_launch(void* const* d_in, const int* in_sizes, int n_in,
                              void* d_out, int out_size)
{
    const float* x  = (const float*)d_in[0];
    const float* wq = (const float*)d_in[1];
    const float* bq = (const float*)d_in[2];
    const float* wk = (const float*)d_in[3];
    const float* bk = (const float*)d_in[4];
    const float* wv = (const float*)d_in[5];
    const float* bv = (const float*)d_in[6];
    const float* wo = (const float*)d_in[7];
    const float* bo = (const float*)d_in[8];
    float* out = (float*)d_out;

    cudaFuncSetAttribute(gemm_bf16split,
                         cudaFuncAttributeMaxDynamicSharedMemorySize, GEMM_SMEM);
    cudaFuncSetAttribute(attn_mma_kernel,
                         cudaFuncAttributeMaxDynamicSharedMemorySize, ATTN_SMEM);

    __nv_bfloat16 *gAhi, *gAlo, *gWhi, *gWlo;
    __nv_bfloat16 *gQh, *gQl, *gKh, *gKl, *gVh, *gVl;
    cudaGetSymbolAddress((void**)&gAhi, g_Ahi);
    cudaGetSymbolAddress((void**)&gAlo, g_Alo);
    cudaGetSymbolAddress((void**)&gWhi, g_Whi);
    cudaGetSymbolAddress((void**)&gWlo, g_Wlo);
    cudaGetSymbolAddress((void**)&gQh, g_Qhi);
    cudaGetSymbolAddress((void**)&gQl, g_Qlo);
    cudaGetSymbolAddress((void**)&gKh, g_Kthi);
    cudaGetSymbolAddress((void**)&gKl, g_Ktlo);
    cudaGetSymbolAddress((void**)&gVh, g_Vhi);
    cudaGetSymbolAddress((void**)&gVl, g_Vlo);

    const int NW = DM * DM;

    // 0) Split inputs into bf16 hi/lo
    split_kernel<<<(Nn*DM/4 + 255)/256, 256>>>(x, gAhi, gAlo, Nn*DM/4);
    split_kernel<<<(NW/4 + 255)/256, 256>>>(wq, gWhi + 0*NW, gWlo + 0*NW, NW/4);
    split_kernel<<<(NW/4 + 255)/256, 256>>>(wk, gWhi + 1*NW, gWlo + 1*NW, NW/4);
    split_kernel<<<(NW/4 + 255)/256, 256>>>(wv, gWhi + 2*NW, gWlo + 2*NW, NW/4);
    split_kernel<<<(NW/4 + 255)/256, 256>>>(wo, gWhi + 3*NW, gWlo + 3*NW, NW/4);

    GArgs ga;
    ga.Ahi = gAhi; ga.Alo = gAlo; ga.Wh = gWhi; ga.Wl = gWlo;
    ga.b0 = bq; ga.b1 = bk; ga.b2 = bv; ga.b3 = bo;
    ga.outf = out;
    ga.q_h = gQh; ga.q_l = gQl; ga.kt_h = gKh; ga.kt_l = gKl;
    ga.v_h = gVh; ga.v_l = gVl;

    // 1) Fused Q/K/V projections (one launch, blockIdx.z selects)
    ga.mode_sel = -1;
    gemm_bf16split<<<dim3(DM/128, Nn/128, 3), 256, GEMM_SMEM>>>(ga);
    // 2) Flash attention on tensor cores (writes g_Ahi/g_Alo)
    attn_mma_kernel<<<dim3(Ss / 128, BH), 256, ATTN_SMEM>>>();
    // 3) Output projection (fp32 out)
    ga.mode_sel = 3;
    gemm_bf16split<<<dim3(DM/128, Nn/128, 1), 256, GEMM_SMEM>>>(ga);
}

// round 11
// speedup vs baseline: 2.3978x; 1.1699x over previous
#include <cuda_runtime.h>
#include <cuda_bf16.h>
#include <math.h>
#include <stdint.h>

// Problem constants
#define Bb 2
#define Ss 2048
#define DM 1024
#define Hh 16
#define Dd 64
#define Nn (Bb*Ss)          // 4096 tokens
#define BH (Bb*Hh)          // 32

#define QSCALE (0.125f * 1.4426950408889634f)   // 1/sqrt(64) * log2(e)

// Scratch (device globals)
__device__ __nv_bfloat16 g_Ahi[Nn*DM], g_Alo[Nn*DM];          // activations (x, then attn-out)
__device__ __nv_bfloat16 g_Whi[4][DM*DM], g_Wlo[4][DM*DM];    // wq, wk, wv, wo
__device__ __nv_bfloat16 g_Qhi[BH*Ss*Dd], g_Qlo[BH*Ss*Dd];    // [bh][s][d], rope'd + scaled
__device__ __nv_bfloat16 g_Khi[BH*Ss*Dd], g_Klo[BH*Ss*Dd];    // [bh][s][d], rope'd
__device__ __nv_bfloat16 g_Vhi[BH*Ss*Dd], g_Vlo[BH*Ss*Dd];    // [bh][s][d]

// ===========================================================================
// PTX helpers
// ===========================================================================
__device__ __forceinline__ uint32_t smem_u32(const void* p) {
    uint32_t a;
    asm("{ .reg .u64 t; cvta.to.shared.u64 t, %1; cvt.u32.u64 %0, t; }"
        : "=r"(a) : "l"(p));
    return a;
}

#define CP_ASYNC16(dst, src) \
    asm volatile("cp.async.cg.shared.global [%0], [%1], 16;" \
                 :: "r"(dst), "l"(src) : "memory")
#define CP_COMMIT() asm volatile("cp.async.commit_group;" ::: "memory")
#define CP_WAIT(n)  asm volatile("cp.async.wait_group %0;" :: "n"(n) : "memory")

__device__ __forceinline__ void ldsm_x4(uint32_t* r, uint32_t addr) {
    asm volatile("ldmatrix.sync.aligned.m8n8.x4.shared.b16 {%0,%1,%2,%3}, [%4];"
                 : "=r"(r[0]), "=r"(r[1]), "=r"(r[2]), "=r"(r[3]) : "r"(addr));
}
__device__ __forceinline__ void ldsm_x4_t(uint32_t* r, uint32_t addr) {
    asm volatile("ldmatrix.sync.aligned.m8n8.x4.trans.shared.b16 {%0,%1,%2,%3}, [%4];"
                 : "=r"(r[0]), "=r"(r[1]), "=r"(r[2]), "=r"(r[3]) : "r"(addr));
}
__device__ __forceinline__ void mma_bf16(float* c, const uint32_t* a,
                                         const uint32_t* b) {
    asm volatile(
        "mma.sync.aligned.m16n8k16.row.col.f32.bf16.bf16.f32 "
        "{%0,%1,%2,%3}, {%4,%5,%6,%7}, {%8,%9}, {%0,%1,%2,%3};"
        : "+f"(c[0]), "+f"(c[1]), "+f"(c[2]), "+f"(c[3])
        : "r"(a[0]), "r"(a[1]), "r"(a[2]), "r"(a[3]), "r"(b[0]), "r"(b[1]));
}
__device__ __forceinline__ float ex2f(float x) {
    float y;
    asm("ex2.approx.ftz.f32 %0, %1;" : "=f"(y) : "f"(x));
    return y;
}
// Split pair (a,b) into packed bf16x2 hi and lo (low half = a)
__device__ __forceinline__ void split2(float a, float b, uint32_t& hp, uint32_t& lp) {
    __nv_bfloat16 ha = __float2bfloat16(a), hb = __float2bfloat16(b);
    float la = a - __bfloat162float(ha);
    float lb = b - __bfloat162float(hb);
    __nv_bfloat162 hv(ha, hb);
    __nv_bfloat162 lv(__float2bfloat16(la), __float2bfloat16(lb));
    hp = *(uint32_t*)&hv;
    lp = *(uint32_t*)&lv;
}

// ===========================================================================
// Fused split: x + 4 weights -> bf16 hi/lo, one launch.
// ===========================================================================
#define XF4 (Nn*DM/4)        // 1048576 float4s
#define WF4 (DM*DM/4)        // 262144 float4s per weight

struct SArgs { const float *x, *w0, *w1, *w2, *w3; };

__global__ void split_all_kernel(SArgs s,
                                 __nv_bfloat16* __restrict__ Ahi,
                                 __nv_bfloat16* __restrict__ Alo,
                                 __nv_bfloat16* __restrict__ Whi,
                                 __nv_bfloat16* __restrict__ Wlo)
{
    const int i = blockIdx.x * blockDim.x + threadIdx.x;
    const float* src; __nv_bfloat16 *hi, *lo; int idx;
    if (i < XF4) {
        src = s.x; hi = Ahi; lo = Alo; idx = i;
    } else {
        const int j = i - XF4;
        const int w = j >> 18;            // WF4 = 2^18
        idx = j & (WF4 - 1);
        src = (w == 0) ? s.w0 : (w == 1) ? s.w1 : (w == 2) ? s.w2 : s.w3;
        hi = Whi + (size_t)w * (DM*DM);
        lo = Wlo + (size_t)w * (DM*DM);
    }
    float4 f = ((const float4*)src)[idx];
    __nv_bfloat16 h[4], l[4];
    float v[4] = {f.x, f.y, f.z, f.w};
#pragma unroll
    for (int j = 0; j < 4; j++) {
        h[j] = __float2bfloat16(v[j]);
        l[j] = __float2bfloat16(v[j] - __bfloat162float(h[j]));
    }
    ((uint2*)hi)[idx] = *(uint2*)h;
    ((uint2*)lo)[idx] = *(uint2*)l;
}

// ===========================================================================
// bf16-split GEMM (mma.sync): 128x128 tile, K-chunk 64, 2-stage, 1 sync/chunk.
// Stage layout (64KB): sAhi 0 | sAlo 16K | sBhi 32K | sBlo 48K
//   sA: 128 rows x 128B (8 units of 8 k-elems), swizzle u ^ (r&7)
//   sB: 64 k-rows x 256B (16 units), swizzle (u&8)|((u&7)^(r&7))
// mode 0: Q -> rope, *QSCALE, split, [bh][s][d]
// mode 1: K -> rope, split, [bh][s][d]
// mode 2: V -> split, [bh][s][d]
// mode 3: O -> fp32 row-major
// ===========================================================================
#define GSTAGE 65536
#define GEMM_SMEM (2*GSTAGE)

struct GArgs {
    const __nv_bfloat16 *Ahi, *Alo, *Wh, *Wl;   // Wh/Wl: base of 4 matrices
    const float *b0, *b1, *b2, *b3;
    float *outf;
    __nv_bfloat16 *q_h, *q_l, *k_h, *k_l, *v_h, *v_l;
    int mode_sel;
};

__global__ __launch_bounds__(256, 1)
void gemm_bf16split(GArgs a)
{
    extern __shared__ __align__(1024) char sm[];
    const uint32_t sb = smem_u32(sm);
    const int mode = (a.mode_sel < 0) ? (int)blockIdx.z : a.mode_sel;

    const __nv_bfloat16* Whi = a.Wh + (size_t)mode * DM * DM;
    const __nv_bfloat16* Wlo = a.Wl + (size_t)mode * DM * DM;
    const float* bias = (mode == 0) ? a.b0 : (mode == 1) ? a.b1
                       : (mode == 2) ? a.b2 : a.b3;
    __nv_bfloat16* outh = (mode == 0) ? a.q_h : (mode == 1) ? a.k_h : a.v_h;
    __nv_bfloat16* outl = (mode == 0) ? a.q_l : (mode == 1) ? a.k_l : a.v_l;

    const int tid  = threadIdx.x;
    const int wid  = tid >> 5;
    const int lane = tid & 31;
    const int wm   = wid >> 1;
    const int wn   = wid & 1;
    const int row0 = blockIdx.y * 128;
    const int col0 = blockIdx.x * 128;

    // ---- cp.async assignments (16 per thread per chunk) ----
    const int a_r  = tid >> 1;            // 0..127
    const int a_u0 = (tid & 1) * 4;       // 0 or 4
    const int b_r  = tid >> 2;            // 0..63
    const int b_u0 = (tid & 3) * 4;       // 0,4,8,12

    const __nv_bfloat16* aH = a.Ahi + (size_t)(row0 + a_r) * DM;
    const __nv_bfloat16* aL = a.Alo + (size_t)(row0 + a_r) * DM;
    const __nv_bfloat16* bH = Whi + (size_t)b_r * DM + col0;
    const __nv_bfloat16* bL = Wlo + (size_t)b_r * DM + col0;

    uint32_t a_dst[4], b_dst[4];
#pragma unroll
    for (int i = 0; i < 4; i++) {
        const int au = a_u0 + i;
        a_dst[i] = (uint32_t)(a_r * 128 + ((au ^ (a_r & 7))) * 16);
        const int bu = b_u0 + i;
        b_dst[i] = (uint32_t)(32768 + b_r * 256
                              + (((bu & 8) | ((bu & 7) ^ (b_r & 7)))) * 16);
    }

    // ---- ldmatrix offsets ----
    const int q8 = lane >> 3;
    const int rr = lane & 7;
    uint32_t offA[4][2];   // [s][mi], hi; lo = +16384
#pragma unroll
    for (int s = 0; s < 4; s++)
#pragma unroll
        for (int mi = 0; mi < 2; mi++) {
            const int arow = wm * 32 + mi * 16 + (q8 & 1) * 8 + rr;
            const int u = 2 * s + (q8 >> 1);
            offA[s][mi] = (uint32_t)(arow * 128 + (u ^ (arow & 7)) * 16);
        }
    uint32_t offB[4][4];   // [s][ng], hi; lo = +16384
#pragma unroll
    for (int s = 0; s < 4; s++)
#pragma unroll
        for (int ng = 0; ng < 4; ng++) {
            const int krow = 16 * s + (q8 & 1) * 8 + rr;
            const int u = wn * 8 + ng * 2 + (q8 >> 1);
            offB[s][ng] = (uint32_t)(32768 + krow * 256
                          + (((u & 8) | ((u & 7) ^ (krow & 7)))) * 16);
        }

    float acc[2][8][4];
#pragma unroll
    for (int mi = 0; mi < 2; mi++)
#pragma unroll
        for (int nf = 0; nf < 8; nf++)
#pragma unroll
            for (int e = 0; e < 4; e++) acc[mi][nf][e] = 0.f;

    // ---- prologue: issue chunk 0 ----
    {
        const uint32_t st = sb;
#pragma unroll
        for (int i = 0; i < 4; i++) {
            const int au = a_u0 + i;
            CP_ASYNC16(st + a_dst[i],         aH + au * 8);
            CP_ASYNC16(st + a_dst[i] + 16384, aL + au * 8);
            const int bu = b_u0 + i;
            CP_ASYNC16(st + b_dst[i],         bH + bu * 8);
            CP_ASYNC16(st + b_dst[i] + 16384, bL + bu * 8);
        }
        CP_COMMIT();
    }

    for (int c = 0; c < 16; c++) {
        CP_WAIT(0);
        __syncthreads();
        if (c + 1 < 16) {
            const uint32_t st = sb + ((c + 1) & 1) * GSTAGE;
            const int k0 = (c + 1) * 64;
#pragma unroll
            for (int i = 0; i < 4; i++) {
                const int au = a_u0 + i;
                CP_ASYNC16(st + a_dst[i],         aH + k0 + au * 8);
                CP_ASYNC16(st + a_dst[i] + 16384, aL + k0 + au * 8);
                const int bu = b_u0 + i;
                CP_ASYNC16(st + b_dst[i],         bH + (size_t)k0 * DM + bu * 8);
                CP_ASYNC16(st + b_dst[i] + 16384, bL + (size_t)k0 * DM + bu * 8);
            }
            CP_COMMIT();
        }

        const uint32_t st = sb + (c & 1) * GSTAGE;
#pragma unroll
        for (int s = 0; s < 4; s++) {
            uint32_t ah[2][4], al[2][4];
#pragma unroll
            for (int mi = 0; mi < 2; mi++) {
                ldsm_x4(ah[mi], st + offA[s][mi]);
                ldsm_x4(al[mi], st + offA[s][mi] + 16384);
            }
#pragma unroll
            for (int ng = 0; ng < 4; ng++) {
                uint32_t bh4[4], bl4[4];
                ldsm_x4_t(bh4, st + offB[s][ng]);
                ldsm_x4_t(bl4, st + offB[s][ng] + 16384);
#pragma unroll
                for (int mi = 0; mi < 2; mi++) {
                    mma_bf16(acc[mi][ng*2],   ah[mi], bh4);
                    mma_bf16(acc[mi][ng*2],   ah[mi], bl4);
                    mma_bf16(acc[mi][ng*2],   al[mi], bh4);
                    mma_bf16(acc[mi][ng*2+1], ah[mi], bh4 + 2);
                    mma_bf16(acc[mi][ng*2+1], ah[mi], bl4 + 2);
                    mma_bf16(acc[mi][ng*2+1], al[mi], bh4 + 2);
                }
            }
        }
    }

    // --- epilogue ----------------------------------------------------------
    float bias_v[16];
#pragma unroll
    for (int nf = 0; nf < 8; nf++)
#pragma unroll
        for (int ec = 0; ec < 2; ec++)
            bias_v[nf*2 + ec] = __ldg(&bias[col0 + wn*64 + nf*8 + (lane&3)*2 + ec]);

    float invf[8];
    if (mode < 2) {
#pragma unroll
        for (int nf = 0; nf < 4; nf++)
#pragma unroll
            for (int ec = 0; ec < 2; ec++) {
                const int j = nf*8 + (lane&3)*2 + ec;
                invf[nf*2 + ec] = powf(10000.f, -(float)j / 32.f);
            }
    }
    const int h_idx = blockIdx.x * 2 + wn;
    const float oscale = (mode == 0) ? QSCALE : 1.f;

#pragma unroll
    for (int mi = 0; mi < 2; mi++) {
#pragma unroll
        for (int er = 0; er < 2; er++) {
            const int m = wm*32 + mi*16 + (lane >> 2) + er*8;
            const int n = row0 + m;
            const int b = n >> 11;
            const int s = n & 2047;
            if (mode < 2) {
                float y1[8], y2[8];
#pragma unroll
                for (int nf = 0; nf < 4; nf++)
#pragma unroll
                    for (int ec = 0; ec < 2; ec++) {
                        const int ii = nf*2 + ec;
                        float sn, cs;
                        sincosf((float)s * invf[ii], &sn, &cs);
                        const float x1 = acc[mi][nf][er*2 + ec]   + bias_v[ii];
                        const float x2 = acc[mi][nf+4][er*2 + ec] + bias_v[ii + 8];
                        y1[ii] = (x1 * cs - x2 * sn) * oscale;
                        y2[ii] = (x2 * cs + x1 * sn) * oscale;
                    }
                __nv_bfloat16* dh = outh + (((size_t)(b*Hh + h_idx))*Ss + s)*Dd;
                __nv_bfloat16* dl = outl + (((size_t)(b*Hh + h_idx))*Ss + s)*Dd;
#pragma unroll
                for (int nf = 0; nf < 4; nf++) {
                    const int d = nf*8 + (lane&3)*2;
                    uint32_t hp, lp;
                    split2(y1[nf*2], y1[nf*2+1], hp, lp);
                    *(uint32_t*)(dh + d) = hp; *(uint32_t*)(dl + d) = lp;
                    split2(y2[nf*2], y2[nf*2+1], hp, lp);
                    *(uint32_t*)(dh + d + 32) = hp; *(uint32_t*)(dl + d + 32) = lp;
                }
            } else if (mode == 2) {
                __nv_bfloat16* dh = outh + (((size_t)(b*Hh + h_idx))*Ss + s)*Dd;
                __nv_bfloat16* dl = outl + (((size_t)(b*Hh + h_idx))*Ss + s)*Dd;
#pragma unroll
                for (int nf = 0; nf < 8; nf++) {
                    const int d = nf*8 + (lane&3)*2;
                    uint32_t hp, lp;
                    split2(acc[mi][nf][er*2] + bias_v[nf*2],
                           acc[mi][nf][er*2+1] + bias_v[nf*2+1], hp, lp);
                    *(uint32_t*)(dh + d) = hp; *(uint32_t*)(dl + d) = lp;
                }
            } else {
                float* dst = a.outf + (size_t)n * DM + col0 + wn*64;
#pragma unroll
                for (int nf = 0; nf < 8; nf++)
#pragma unroll
                    for (int ec = 0; ec < 2; ec++)
                        dst[nf*8 + (lane&3)*2 + ec] =
                            acc[mi][nf][er*2 + ec] + bias_v[nf*2 + ec];
            }
        }
    }
}

// ===========================================================================
// Flash attention on mma.sync, FA2-style warp-row ownership.
// K stored [bh][s][d] (natural) -> QK^T B-frags via NON-trans ldmatrix.
// 2-stage KV, ONE __syncthreads per tile.
// smem: Q 32KB | K/V double buffer 2x64KB = 160KB
//   K tile: rows=s (128 x 128B, swizzle u^(s&7)), hi at 0, lo +16384
//   V tile: same layout at +32768
// ===========================================================================
#define AQ_OFF    0
#define AKV_OFF   32768
#define AKV_SZ    65536
#define ATTN_SMEM (AKV_OFF + 2*AKV_SZ)

__global__ __launch_bounds__(256, 1)
void attn_mma_kernel()
{
    extern __shared__ __align__(1024) char sm[];
    const uint32_t sb = smem_u32(sm);
    const int tid  = threadIdx.x;
    const int wid  = tid >> 5;
    const int lane = tid & 31;
    const int qt   = blockIdx.x;
    const int bh   = blockIdx.y;
    const int b    = bh >> 4;
    const int h    = bh & 15;

    const int q8 = lane >> 3;
    const int rr = lane & 7;

    // cp.async assignments: thread covers one row (s) of K and V, hi or lo
    const int ca  = tid >> 7;          // 0 = hi array, 1 = lo array
    const int ct  = tid & 127;         // row within tile
    const __nv_bfloat16* gq = (ca ? g_Qlo : g_Qhi) + ((size_t)bh*Ss + qt*128 + ct)*Dd;
    const __nv_bfloat16* gk = (ca ? g_Klo : g_Khi) + ((size_t)bh*Ss + ct)*Dd;
    const __nv_bfloat16* gv = (ca ? g_Vlo : g_Vhi) + ((size_t)bh*Ss + ct)*Dd;

    uint32_t qdst[8], kdst[8], vdst[8];
#pragma unroll
    for (int u = 0; u < 8; u++) {
        const uint32_t sw = (uint32_t)((u ^ (ct & 7)) * 16);
        qdst[u] = (uint32_t)(AQ_OFF + ca*16384 + ct*128) + sw;
        kdst[u] = (uint32_t)(ca*16384 + ct*128) + sw;
        vdst[u] = (uint32_t)(32768 + ca*16384 + ct*128) + sw;
    }

    // Q fragment ldmatrix offsets (warp rows wid*16..+15)
    uint32_t qa_off[4];
#pragma unroll
    for (int kc = 0; kc < 4; kc++) {
        const int row = wid*16 + (q8 & 1)*8 + rr;
        const int u = kc*2 + (q8 >> 1);
        qa_off[kc] = (uint32_t)(AQ_OFF + row*128 + ((u ^ (row & 7))) * 16);
    }
    // K b-frag offsets (non-trans): n-row = s, k = d
    uint32_t kb_off[4][8];
#pragma unroll
    for (int kc = 0; kc < 4; kc++)
#pragma unroll
        for (int ng = 0; ng < 8; ng++) {
            const int nrow = ng*16 + (q8 >> 1)*8 + rr;
            const int u = kc*2 + (q8 & 1);
            kb_off[kc][ng] = (uint32_t)(nrow*128 + ((u ^ (nrow & 7))) * 16);
        }
    // V b-frag offsets (trans): rows = s
    uint32_t vb_off[8][4];
#pragma unroll
    for (int kc = 0; kc < 8; kc++)
#pragma unroll
        for (int ng = 0; ng < 4; ng++) {
            const int vr = kc*16 + (q8 & 1)*8 + rr;
            const int u  = ng*2 + (q8 >> 1);
            vb_off[kc][ng] = (uint32_t)(32768 + vr*128 + ((u ^ (vr & 7))) * 16);
        }

    // prologue: load Q + tile 0
#pragma unroll
    for (int u = 0; u < 8; u++) CP_ASYNC16(sb + qdst[u], gq + u*8);
#pragma unroll
    for (int u = 0; u < 8; u++) {
        CP_ASYNC16(sb + AKV_OFF + kdst[u], gk + u*8);
        CP_ASYNC16(sb + AKV_OFF + vdst[u], gv + u*8);
    }
    CP_COMMIT();

    uint32_t qh_f[4][4], ql_f[4][4];     // Q frags cached across tiles
    float o_acc[8][4];
    float m_i[2], l_i[2];
#pragma unroll
    for (int er = 0; er < 2; er++) { m_i[er] = -1e30f; l_i[er] = 0.f; }
#pragma unroll
    for (int nf = 0; nf < 8; nf++)
#pragma unroll
        for (int e = 0; e < 4; e++) o_acc[nf][e] = 0.f;

    for (int nt = 0; nt < 16; nt++) {
        CP_WAIT(0);
        __syncthreads();

        if (nt == 0) {
#pragma unroll
            for (int kc = 0; kc < 4; kc++) {
                ldsm_x4(qh_f[kc], sb + qa_off[kc]);
                ldsm_x4(ql_f[kc], sb + qa_off[kc] + 16384);
            }
        }
        if (nt + 1 < 16) {
            const uint32_t kb = sb + AKV_OFF + ((nt + 1) & 1) * AKV_SZ;
            const size_t s0 = (size_t)(nt + 1) * 128 * Dd;
#pragma unroll
            for (int u = 0; u < 8; u++) {
                CP_ASYNC16(kb + kdst[u], gk + s0 + u*8);
                CP_ASYNC16(kb + vdst[u], gv + s0 + u*8);
            }
            CP_COMMIT();
        }

        const uint32_t kbase = sb + AKV_OFF + (nt & 1) * AKV_SZ;

        // ---- S = Q K^T  (16 rows x 128 cols per warp) ----
        float sacc[16][4];
#pragma unroll
        for (int nf = 0; nf < 16; nf++)
#pragma unroll
            for (int e = 0; e < 4; e++) sacc[nf][e] = 0.f;

#pragma unroll
        for (int kc = 0; kc < 4; kc++) {
#pragma unroll
            for (int ng = 0; ng < 8; ng++) {
                const uint32_t ko = kbase + kb_off[kc][ng];
                uint32_t kh[4], kl[4];
                ldsm_x4(kh, ko);
                ldsm_x4(kl, ko + 16384);
                mma_bf16(sacc[ng*2],   qh_f[kc], kh);
                mma_bf16(sacc[ng*2],   qh_f[kc], kl);
                mma_bf16(sacc[ng*2],   ql_f[kc], kh);
                mma_bf16(sacc[ng*2+1], qh_f[kc], kh + 2);
                mma_bf16(sacc[ng*2+1], qh_f[kc], kl + 2);
                mma_bf16(sacc[ng*2+1], ql_f[kc], kh + 2);
            }
        }

        // ---- online softmax (fully in-register, quad shfl) ----
        float m_new[2], sc[2];
#pragma unroll
        for (int er = 0; er < 2; er++) {
            float mx = -1e30f;
#pragma unroll
            for (int nf = 0; nf < 16; nf++) {
                mx = fmaxf(mx, sacc[nf][er*2]);
                mx = fmaxf(mx, sacc[nf][er*2+1]);
            }
            mx = fmaxf(mx, __shfl_xor_sync(0xffffffffu, mx, 1));
            mx = fmaxf(mx, __shfl_xor_sync(0xffffffffu, mx, 2));
            m_new[er] = fmaxf(m_i[er], mx);
            sc[er] = ex2f(m_i[er] - m_new[er]);
        }
#pragma unroll
        for (int er = 0; er < 2; er++) {
            float rs = 0.f;
#pragma unroll
            for (int nf = 0; nf < 16; nf++) {
#pragma unroll
                for (int ec = 0; ec < 2; ec++) {
                    float p = ex2f(sacc[nf][er*2+ec] - m_new[er]);
                    sacc[nf][er*2+ec] = p;
                    rs += p;
                }
            }
            rs += __shfl_xor_sync(0xffffffffu, rs, 1);
            rs += __shfl_xor_sync(0xffffffffu, rs, 2);
            l_i[er] = l_i[er] * sc[er] + rs;
            m_i[er] = m_new[er];
#pragma unroll
            for (int nf = 0; nf < 8; nf++) {
                o_acc[nf][er*2]   *= sc[er];
                o_acc[nf][er*2+1] *= sc[er];
            }
        }

        // ---- O += P V (P in registers: C-frag -> A-frag) ----
#pragma unroll
        for (int kc = 0; kc < 8; kc++) {
            uint32_t ph[4], pl[4];
            const float* cE = sacc[2*kc];
            const float* cO = sacc[2*kc+1];
            split2(cE[0], cE[1], ph[0], pl[0]);
            split2(cE[2], cE[3], ph[1], pl[1]);
            split2(cO[0], cO[1], ph[2], pl[2]);
            split2(cO[2], cO[3], ph[3], pl[3]);
#pragma unroll
            for (int ng = 0; ng < 4; ng++) {
                const uint32_t vo = kbase + vb_off[kc][ng];
                uint32_t vh[4], vl[4];
                ldsm_x4_t(vh, vo);
                ldsm_x4_t(vl, vo + 16384);
                mma_bf16(o_acc[ng*2],   ph, vh);
                mma_bf16(o_acc[ng*2],   pl, vh);
                mma_bf16(o_acc[ng*2],   ph, vl);
                mma_bf16(o_acc[ng*2+1], ph, vh + 2);
                mma_bf16(o_acc[ng*2+1], pl, vh + 2);
                mma_bf16(o_acc[ng*2+1], ph, vl + 2);
            }
        }
    }

    // ---- epilogue: per-warp direct write ----
#pragma unroll
    for (int er = 0; er < 2; er++) {
        const int r = wid*16 + (lane >> 2) + er*8;
        const float inv = 1.f / l_i[er];
        const size_t nrow = (size_t)(b*Ss + qt*128 + r) * DM + h*64;
#pragma unroll
        for (int nf = 0; nf < 8; nf++) {
            const int col = nf*8 + (lane & 3)*2;
            const float v0 = o_acc[nf][er*2]   * inv;
            const float v1 = o_acc[nf][er*2+1] * inv;
            uint32_t hp, lp;
            split2(v0, v1, hp, lp);
            *(uint32_t*)(g_Ahi + nrow + col) = hp;
            *(uint32_t*)(g_Alo + nrow + col) = lp;
        }
    }
}

// ---------------------------------------------------------------------------
extern "C" void kernel_launch(void* const* d_in, const int* in_sizes, int n_in,
                              void* d_out, int out_size)
{
    const float* x  = (const float*)d_in[0];
    const float* wq = (const float*)d_in[1];
    const float* bq = (const float*)d_in[2];
    const float* wk = (const float*)d_in[3];
    const float* bk = (const float*)d_in[4];
    const float* wv = (const float*)d_in[5];
    const float* bv = (const float*)d_in[6];
    const float* wo = (const float*)d_in[7];
    const float* bo = (const float*)d_in[8];
    float* out = (float*)d_out;

    cudaFuncSetAttribute(gemm_bf16split,
                         cudaFuncAttributeMaxDynamicSharedMemorySize, GEMM_SMEM);
    cudaFuncSetAttribute(attn_mma_kernel,
                         cudaFuncAttributeMaxDynamicSharedMemorySize, ATTN_SMEM);

    __nv_bfloat16 *gAhi, *gAlo, *gWhi, *gWlo;
    __nv_bfloat16 *gQh, *gQl, *gKh, *gKl, *gVh, *gVl;
    cudaGetSymbolAddress((void**)&gAhi, g_Ahi);
    cudaGetSymbolAddress((void**)&gAlo, g_Alo);
    cudaGetSymbolAddress((void**)&gWhi, g_Whi);
    cudaGetSymbolAddress((void**)&gWlo, g_Wlo);
    cudaGetSymbolAddress((void**)&gQh, g_Qhi);
    cudaGetSymbolAddress((void**)&gQl, g_Qlo);
    cudaGetSymbolAddress((void**)&gKh, g_Khi);
    cudaGetSymbolAddress((void**)&gKl, g_Klo);
    cudaGetSymbolAddress((void**)&gVh, g_Vhi);
    cudaGetSymbolAddress((void**)&gVl, g_Vlo);

    // 0) Split x + all 4 weights in ONE launch
    SArgs sa; sa.x = x; sa.w0 = wq; sa.w1 = wk; sa.w2 = wv; sa.w3 = wo;
    split_all_kernel<<<(XF4 + 4*WF4) / 256, 256>>>(sa, gAhi, gAlo, gWhi, gWlo);

    GArgs ga;
    ga.Ahi = gAhi; ga.Alo = gAlo; ga.Wh = gWhi; ga.Wl = gWlo;
    ga.b0 = bq; ga.b1 = bk; ga.b2 = bv; ga.b3 = bo;
    ga.outf = out;
    ga.q_h = gQh; ga.q_l = gQl; ga.k_h = gKh; ga.k_l = gKl;
    ga.v_h = gVh; ga.v_l = gVl;

    // 1) Fused Q/K/V projections (one launch, blockIdx.z selects)
    ga.mode_sel = -1;
    gemm_bf16split<<<dim3(DM/128, Nn/128, 3), 256, GEMM_SMEM>>>(ga);
    // 2) Flash attention on tensor cores (writes g_Ahi/g_Alo)
    attn_mma_kernel<<<dim3(Ss / 128, BH), 256, ATTN_SMEM>>>();
    // 3) Output projection (fp32 out)
    ga.mode_sel = 3;
    gemm_bf16split<<<dim3(DM/128, Nn/128, 1), 256, GEMM_SMEM>>>(ga);
}

// round 12
// speedup vs baseline: 2.4067x; 1.0037x over previous
#include <cuda_runtime.h>
#include <cuda_bf16.h>
#include <math.h>
#include <stdint.h>

// Problem constants
#define Bb 2
#define Ss 2048
#define DM 1024
#define Hh 16
#define Dd 64
#define Nn (Bb*Ss)          // 4096 tokens
#define BH (Bb*Hh)          // 32

#define QSCALE (0.125f * 1.4426950408889634f)   // 1/sqrt(64) * log2(e)

// Scratch (device globals)
__device__ __nv_bfloat16 g_Ahi[Nn*DM], g_Alo[Nn*DM];          // activations (x, then attn-out)
__device__ __nv_bfloat16 g_Whi[4][DM*DM], g_Wlo[4][DM*DM];    // wq, wk, wv, wo
__device__ __nv_bfloat16 g_Qhi[BH*Ss*Dd], g_Qlo[BH*Ss*Dd];    // [bh][s][d], rope'd + scaled
__device__ __nv_bfloat16 g_Khi[BH*Ss*Dd], g_Klo[BH*Ss*Dd];    // [bh][s][d], rope'd
__device__ __nv_bfloat16 g_Vhi[BH*Ss*Dd], g_Vlo[BH*Ss*Dd];    // [bh][s][d]

// ===========================================================================
// PTX helpers
// ===========================================================================
__device__ __forceinline__ uint32_t smem_u32(const void* p) {
    uint32_t a;
    asm("{ .reg .u64 t; cvta.to.shared.u64 t, %1; cvt.u32.u64 %0, t; }"
        : "=r"(a) : "l"(p));
    return a;
}

#define CP_ASYNC16(dst, src) \
    asm volatile("cp.async.cg.shared.global [%0], [%1], 16;" \
                 :: "r"(dst), "l"(src) : "memory")
#define CP_COMMIT() asm volatile("cp.async.commit_group;" ::: "memory")
#define CP_WAIT(n)  asm volatile("cp.async.wait_group %0;" :: "n"(n) : "memory")

__device__ __forceinline__ void ldsm_x4(uint32_t* r, uint32_t addr) {
    asm volatile("ldmatrix.sync.aligned.m8n8.x4.shared.b16 {%0,%1,%2,%3}, [%4];"
                 : "=r"(r[0]), "=r"(r[1]), "=r"(r[2]), "=r"(r[3]) : "r"(addr));
}
__device__ __forceinline__ void ldsm_x4_t(uint32_t* r, uint32_t addr) {
    asm volatile("ldmatrix.sync.aligned.m8n8.x4.trans.shared.b16 {%0,%1,%2,%3}, [%4];"
                 : "=r"(r[0]), "=r"(r[1]), "=r"(r[2]), "=r"(r[3]) : "r"(addr));
}
__device__ __forceinline__ void mma_bf16(float* c, const uint32_t* a,
                                         const uint32_t* b) {
    asm volatile(
        "mma.sync.aligned.m16n8k16.row.col.f32.bf16.bf16.f32 "
        "{%0,%1,%2,%3}, {%4,%5,%6,%7}, {%8,%9}, {%0,%1,%2,%3};"
        : "+f"(c[0]), "+f"(c[1]), "+f"(c[2]), "+f"(c[3])
        : "r"(a[0]), "r"(a[1]), "r"(a[2]), "r"(a[3]), "r"(b[0]), "r"(b[1]));
}
__device__ __forceinline__ float ex2f(float x) {
    float y;
    asm("ex2.approx.ftz.f32 %0, %1;" : "=f"(y) : "f"(x));
    return y;
}
// Split pair (a,b) into packed bf16x2 hi and lo (low half = a)
__device__ __forceinline__ void split2(float a, float b, uint32_t& hp, uint32_t& lp) {
    __nv_bfloat16 ha = __float2bfloat16(a), hb = __float2bfloat16(b);
    float la = a - __bfloat162float(ha);
    float lb = b - __bfloat162float(hb);
    __nv_bfloat162 hv(ha, hb);
    __nv_bfloat162 lv(__float2bfloat16(la), __float2bfloat16(lb));
    hp = *(uint32_t*)&hv;
    lp = *(uint32_t*)&lv;
}

// ===========================================================================
// Fused split: x + 4 weights -> bf16 hi/lo, one launch.
// ===========================================================================
#define XF4 (Nn*DM/4)        // 1048576 float4s
#define WF4 (DM*DM/4)        // 262144 float4s per weight

struct SArgs { const float *x, *w0, *w1, *w2, *w3; };

__global__ void split_all_kernel(SArgs s,
                                 __nv_bfloat16* __restrict__ Ahi,
                                 __nv_bfloat16* __restrict__ Alo,
                                 __nv_bfloat16* __restrict__ Whi,
                                 __nv_bfloat16* __restrict__ Wlo)
{
    const int i = blockIdx.x * blockDim.x + threadIdx.x;
    const float* src; __nv_bfloat16 *hi, *lo; int idx;
    if (i < XF4) {
        src = s.x; hi = Ahi; lo = Alo; idx = i;
    } else {
        const int j = i - XF4;
        const int w = j >> 18;            // WF4 = 2^18
        idx = j & (WF4 - 1);
        src = (w == 0) ? s.w0 : (w == 1) ? s.w1 : (w == 2) ? s.w2 : s.w3;
        hi = Whi + (size_t)w * (DM*DM);
        lo = Wlo + (size_t)w * (DM*DM);
    }
    float4 f = ((const float4*)src)[idx];
    __nv_bfloat16 h[4], l[4];
    float v[4] = {f.x, f.y, f.z, f.w};
#pragma unroll
    for (int j = 0; j < 4; j++) {
        h[j] = __float2bfloat16(v[j]);
        l[j] = __float2bfloat16(v[j] - __bfloat162float(h[j]));
    }
    ((uint2*)hi)[idx] = *(uint2*)h;
    ((uint2*)lo)[idx] = *(uint2*)l;
}

// ===========================================================================
// bf16-split GEMM (mma.sync): 128x128 tile, K-chunk 64, 2-stage, 1 sync/chunk.
// Software-pipelined fragment loads (volatile-asm source order = SASS order).
// Stage layout (64KB): sAhi 0 | sAlo 16K | sBhi 32K | sBlo 48K
// ===========================================================================
#define GSTAGE 65536
#define GEMM_SMEM (2*GSTAGE)

struct GArgs {
    const __nv_bfloat16 *Ahi, *Alo, *Wh, *Wl;   // Wh/Wl: base of 4 matrices
    const float *b0, *b1, *b2, *b3;
    float *outf;
    __nv_bfloat16 *q_h, *q_l, *k_h, *k_l, *v_h, *v_l;
    int mode_sel;
};

__global__ __launch_bounds__(256, 1)
void gemm_bf16split(GArgs a)
{
    extern __shared__ __align__(1024) char sm[];
    const uint32_t sb = smem_u32(sm);
    const int mode = (a.mode_sel < 0) ? (int)blockIdx.z : a.mode_sel;

    const __nv_bfloat16* Whi = a.Wh + (size_t)mode * DM * DM;
    const __nv_bfloat16* Wlo = a.Wl + (size_t)mode * DM * DM;
    const float* bias = (mode == 0) ? a.b0 : (mode == 1) ? a.b1
                       : (mode == 2) ? a.b2 : a.b3;
    __nv_bfloat16* outh = (mode == 0) ? a.q_h : (mode == 1) ? a.k_h : a.v_h;
    __nv_bfloat16* outl = (mode == 0) ? a.q_l : (mode == 1) ? a.k_l : a.v_l;

    const int tid  = threadIdx.x;
    const int wid  = tid >> 5;
    const int lane = tid & 31;
    const int wm   = wid >> 1;
    const int wn   = wid & 1;
    const int row0 = blockIdx.y * 128;
    const int col0 = blockIdx.x * 128;

    // ---- cp.async assignments (16 per thread per chunk) ----
    const int a_r  = tid >> 1;            // 0..127
    const int a_u0 = (tid & 1) * 4;       // 0 or 4
    const int b_r  = tid >> 2;            // 0..63
    const int b_u0 = (tid & 3) * 4;       // 0,4,8,12

    const __nv_bfloat16* aH = a.Ahi + (size_t)(row0 + a_r) * DM;
    const __nv_bfloat16* aL = a.Alo + (size_t)(row0 + a_r) * DM;
    const __nv_bfloat16* bH = Whi + (size_t)b_r * DM + col0;
    const __nv_bfloat16* bL = Wlo + (size_t)b_r * DM + col0;

    uint32_t a_dst[4], b_dst[4];
#pragma unroll
    for (int i = 0; i < 4; i++) {
        const int au = a_u0 + i;
        a_dst[i] = (uint32_t)(a_r * 128 + ((au ^ (a_r & 7))) * 16);
        const int bu = b_u0 + i;
        b_dst[i] = (uint32_t)(32768 + b_r * 256
                              + (((bu & 8) | ((bu & 7) ^ (b_r & 7)))) * 16);
    }

    // ---- ldmatrix offsets ----
    const int q8 = lane >> 3;
    const int rr = lane & 7;
    uint32_t offA[4][2];   // [s][mi], hi; lo = +16384
#pragma unroll
    for (int s = 0; s < 4; s++)
#pragma unroll
        for (int mi = 0; mi < 2; mi++) {
            const int arow = wm * 32 + mi * 16 + (q8 & 1) * 8 + rr;
            const int u = 2 * s + (q8 >> 1);
            offA[s][mi] = (uint32_t)(arow * 128 + (u ^ (arow & 7)) * 16);
        }
    uint32_t offB[4][4];   // [s][ng], hi; lo = +16384
#pragma unroll
    for (int s = 0; s < 4; s++)
#pragma unroll
        for (int ng = 0; ng < 4; ng++) {
            const int krow = 16 * s + (q8 & 1) * 8 + rr;
            const int u = wn * 8 + ng * 2 + (q8 >> 1);
            offB[s][ng] = (uint32_t)(32768 + krow * 256
                          + (((u & 8) | ((u & 7) ^ (krow & 7)))) * 16);
        }

    float acc[2][8][4];
#pragma unroll
    for (int mi = 0; mi < 2; mi++)
#pragma unroll
        for (int nf = 0; nf < 8; nf++)
#pragma unroll
            for (int e = 0; e < 4; e++) acc[mi][nf][e] = 0.f;

    // ---- prologue: issue chunk 0 ----
    {
        const uint32_t st = sb;
#pragma unroll
        for (int i = 0; i < 4; i++) {
            const int au = a_u0 + i;
            CP_ASYNC16(st + a_dst[i],         aH + au * 8);
            CP_ASYNC16(st + a_dst[i] + 16384, aL + au * 8);
            const int bu = b_u0 + i;
            CP_ASYNC16(st + b_dst[i],         bH + bu * 8);
            CP_ASYNC16(st + b_dst[i] + 16384, bL + bu * 8);
        }
        CP_COMMIT();
    }

    for (int c = 0; c < 16; c++) {
        CP_WAIT(0);
        __syncthreads();
        const uint32_t st = sb + (c & 1) * GSTAGE;

        // Fragment double buffers: [buf][hi/lo][...]
        uint32_t Af[2][2][2][4];   // [buf][arr][mi][4]
        uint32_t Bf[2][2][4];      // [buf][arr][4]

        // preload step 0 frags (latency hides behind cp.async issue below)
#pragma unroll
        for (int mi = 0; mi < 2; mi++) {
            ldsm_x4(Af[0][0][mi], st + offA[0][mi]);
            ldsm_x4(Af[0][1][mi], st + offA[0][mi] + 16384);
        }
        ldsm_x4_t(Bf[0][0], st + offB[0][0]);
        ldsm_x4_t(Bf[0][1], st + offB[0][0] + 16384);

        if (c + 1 < 16) {
            const uint32_t st2 = sb + ((c + 1) & 1) * GSTAGE;
            const int k0 = (c + 1) * 64;
#pragma unroll
            for (int i = 0; i < 4; i++) {
                const int au = a_u0 + i;
                CP_ASYNC16(st2 + a_dst[i],         aH + k0 + au * 8);
                CP_ASYNC16(st2 + a_dst[i] + 16384, aL + k0 + au * 8);
                const int bu = b_u0 + i;
                CP_ASYNC16(st2 + b_dst[i],         bH + (size_t)k0 * DM + bu * 8);
                CP_ASYNC16(st2 + b_dst[i] + 16384, bL + (size_t)k0 * DM + bu * 8);
            }
            CP_COMMIT();
        }

        // 16 pipelined (s, ng) steps
#pragma unroll
        for (int stp = 0; stp < 16; stp++) {
            const int s  = stp >> 2;
            const int ng = stp & 3;
            const int cb = stp & 1;       // B buffer
            const int ab = s & 1;         // A buffer
            if (stp < 15) {               // prefetch next step's B frags
                const int s2 = (stp + 1) >> 2, ng2 = (stp + 1) & 3;
                ldsm_x4_t(Bf[cb ^ 1][0], st + offB[s2][ng2]);
                ldsm_x4_t(Bf[cb ^ 1][1], st + offB[s2][ng2] + 16384);
            }
            if (ng == 2 && s < 3) {       // prefetch next s's A frags
#pragma unroll
                for (int mi = 0; mi < 2; mi++) {
                    ldsm_x4(Af[ab ^ 1][0][mi], st + offA[s + 1][mi]);
                    ldsm_x4(Af[ab ^ 1][1][mi], st + offA[s + 1][mi] + 16384);
                }
            }
            // 12 MMAs, same-accumulator distance 4
            mma_bf16(acc[0][ng*2],   Af[ab][0][0], Bf[cb][0]);
            mma_bf16(acc[0][ng*2+1], Af[ab][0][0], Bf[cb][0] + 2);
            mma_bf16(acc[1][ng*2],   Af[ab][0][1], Bf[cb][0]);
            mma_bf16(acc[1][ng*2+1], Af[ab][0][1], Bf[cb][0] + 2);
            mma_bf16(acc[0][ng*2],   Af[ab][0][0], Bf[cb][1]);
            mma_bf16(acc[0][ng*2+1], Af[ab][0][0], Bf[cb][1] + 2);
            mma_bf16(acc[1][ng*2],   Af[ab][0][1], Bf[cb][1]);
            mma_bf16(acc[1][ng*2+1], Af[ab][0][1], Bf[cb][1] + 2);
            mma_bf16(acc[0][ng*2],   Af[ab][1][0], Bf[cb][0]);
            mma_bf16(acc[0][ng*2+1], Af[ab][1][0], Bf[cb][0] + 2);
            mma_bf16(acc[1][ng*2],   Af[ab][1][1], Bf[cb][0]);
            mma_bf16(acc[1][ng*2+1], Af[ab][1][1], Bf[cb][0] + 2);
        }
    }

    // --- epilogue ----------------------------------------------------------
    float bias_v[16];
#pragma unroll
    for (int nf = 0; nf < 8; nf++)
#pragma unroll
        for (int ec = 0; ec < 2; ec++)
            bias_v[nf*2 + ec] = __ldg(&bias[col0 + wn*64 + nf*8 + (lane&3)*2 + ec]);

    float invf[8];
    if (mode < 2) {
#pragma unroll
        for (int nf = 0; nf < 4; nf++)
#pragma unroll
            for (int ec = 0; ec < 2; ec++) {
                const int j = nf*8 + (lane&3)*2 + ec;
                invf[nf*2 + ec] = powf(10000.f, -(float)j / 32.f);
            }
    }
    const int h_idx = blockIdx.x * 2 + wn;
    const float oscale = (mode == 0) ? QSCALE : 1.f;

#pragma unroll
    for (int mi = 0; mi < 2; mi++) {
#pragma unroll
        for (int er = 0; er < 2; er++) {
            const int m = wm*32 + mi*16 + (lane >> 2) + er*8;
            const int n = row0 + m;
            const int b = n >> 11;
            const int s = n & 2047;
            if (mode < 2) {
                float y1[8], y2[8];
#pragma unroll
                for (int nf = 0; nf < 4; nf++)
#pragma unroll
                    for (int ec = 0; ec < 2; ec++) {
                        const int ii = nf*2 + ec;
                        float sn, cs;
                        sincosf((float)s * invf[ii], &sn, &cs);
                        const float x1 = acc[mi][nf][er*2 + ec]   + bias_v[ii];
                        const float x2 = acc[mi][nf+4][er*2 + ec] + bias_v[ii + 8];
                        y1[ii] = (x1 * cs - x2 * sn) * oscale;
                        y2[ii] = (x2 * cs + x1 * sn) * oscale;
                    }
                __nv_bfloat16* dh = outh + (((size_t)(b*Hh + h_idx))*Ss + s)*Dd;
                __nv_bfloat16* dl = outl + (((size_t)(b*Hh + h_idx))*Ss + s)*Dd;
#pragma unroll
                for (int nf = 0; nf < 4; nf++) {
                    const int d = nf*8 + (lane&3)*2;
                    uint32_t hp, lp;
                    split2(y1[nf*2], y1[nf*2+1], hp, lp);
                    *(uint32_t*)(dh + d) = hp; *(uint32_t*)(dl + d) = lp;
                    split2(y2[nf*2], y2[nf*2+1], hp, lp);
                    *(uint32_t*)(dh + d + 32) = hp; *(uint32_t*)(dl + d + 32) = lp;
                }
            } else if (mode == 2) {
                __nv_bfloat16* dh = outh + (((size_t)(b*Hh + h_idx))*Ss + s)*Dd;
                __nv_bfloat16* dl = outl + (((size_t)(b*Hh + h_idx))*Ss + s)*Dd;
#pragma unroll
                for (int nf = 0; nf < 8; nf++) {
                    const int d = nf*8 + (lane&3)*2;
                    uint32_t hp, lp;
                    split2(acc[mi][nf][er*2] + bias_v[nf*2],
                           acc[mi][nf][er*2+1] + bias_v[nf*2+1], hp, lp);
                    *(uint32_t*)(dh + d) = hp; *(uint32_t*)(dl + d) = lp;
                }
            } else {
                float* dst = a.outf + (size_t)n * DM + col0 + wn*64;
#pragma unroll
                for (int nf = 0; nf < 8; nf++)
#pragma unroll
                    for (int ec = 0; ec < 2; ec++)
                        dst[nf*8 + (lane&3)*2 + ec] =
                            acc[mi][nf][er*2 + ec] + bias_v[nf*2 + ec];
            }
        }
    }
}

// ===========================================================================
// Flash attention on mma.sync, FA2-style warp-row ownership, software-
// pipelined fragment loads. K stored [bh][s][d] -> non-trans ldmatrix b-frags.
// smem: Q 32KB | K/V double buffer 2x64KB = 160KB
// ===========================================================================
#define AQ_OFF    0
#define AKV_OFF   32768
#define AKV_SZ    65536
#define ATTN_SMEM (AKV_OFF + 2*AKV_SZ)

__global__ __launch_bounds__(256, 1)
void attn_mma_kernel()
{
    extern __shared__ __align__(1024) char sm[];
    const uint32_t sb = smem_u32(sm);
    const int tid  = threadIdx.x;
    const int wid  = tid >> 5;
    const int lane = tid & 31;
    const int qt   = blockIdx.x;
    const int bh   = blockIdx.y;
    const int b    = bh >> 4;
    const int h    = bh & 15;

    const int q8  = lane >> 3;
    const int rr  = lane & 7;
    const int q8l = q8 & 1;
    const int q8h = q8 >> 1;

    // cp.async assignments: thread covers one row (s) of K and V, hi or lo
    const int ca  = tid >> 7;          // 0 = hi array, 1 = lo array
    const int ct  = tid & 127;         // row within tile
    const int c7  = ct & 7;
    const __nv_bfloat16* gq = (ca ? g_Qlo : g_Qhi) + ((size_t)bh*Ss + qt*128 + ct)*Dd;
    const __nv_bfloat16* gk = (ca ? g_Klo : g_Khi) + ((size_t)bh*Ss + ct)*Dd;
    const __nv_bfloat16* gv = (ca ? g_Vlo : g_Vhi) + ((size_t)bh*Ss + ct)*Dd;

    const uint32_t qb0 = (uint32_t)(AQ_OFF + ca*16384 + ct*128);
    const uint32_t kb0 = (uint32_t)(ca*16384 + ct*128);
    const uint32_t vb0 = (uint32_t)(32768 + ca*16384 + ct*128);

    // ldmatrix lane bases
    const uint32_t qrow_b = (uint32_t)((wid*16 + q8l*8 + rr) * 128);  // Q a-frag rows
    const uint32_t krow_b = (uint32_t)((q8h*8 + rr) * 128);           // K b-frag rows
    const uint32_t vrow_b = (uint32_t)((q8l*8 + rr) * 128);           // V b-frag rows

    // prologue: load Q + tile 0
#pragma unroll
    for (int u = 0; u < 8; u++) {
        const uint32_t sw = (uint32_t)((u ^ c7) * 16);
        CP_ASYNC16(sb + qb0 + sw, gq + u*8);
    }
#pragma unroll
    for (int u = 0; u < 8; u++) {
        const uint32_t sw = (uint32_t)((u ^ c7) * 16);
        CP_ASYNC16(sb + AKV_OFF + kb0 + sw, gk + u*8);
        CP_ASYNC16(sb + AKV_OFF + vb0 + sw, gv + u*8);
    }
    CP_COMMIT();

    uint32_t qh_f[4][4], ql_f[4][4];     // Q frags cached across tiles
    float o_acc[8][4];
    float m_i[2], l_i[2];
#pragma unroll
    for (int er = 0; er < 2; er++) { m_i[er] = -1e30f; l_i[er] = 0.f; }
#pragma unroll
    for (int nf = 0; nf < 8; nf++)
#pragma unroll
        for (int e = 0; e < 4; e++) o_acc[nf][e] = 0.f;

    for (int nt = 0; nt < 16; nt++) {
        CP_WAIT(0);
        __syncthreads();

        if (nt == 0) {
#pragma unroll
            for (int kc = 0; kc < 4; kc++) {
                const uint32_t qa = AQ_OFF + qrow_b + (uint32_t)((((kc*2 + q8h) ^ rr)) * 16);
                ldsm_x4(qh_f[kc], sb + qa);
                ldsm_x4(ql_f[kc], sb + qa + 16384);
            }
        }
        if (nt + 1 < 16) {
            const uint32_t kb = sb + AKV_OFF + ((nt + 1) & 1) * AKV_SZ;
            const size_t s0 = (size_t)(nt + 1) * 128 * Dd;
#pragma unroll
            for (int u = 0; u < 8; u++) {
                const uint32_t sw = (uint32_t)((u ^ c7) * 16);
                CP_ASYNC16(kb + kb0 + sw, gk + s0 + u*8);
                CP_ASYNC16(kb + vb0 + sw, gv + s0 + u*8);
            }
            CP_COMMIT();
        }

        const uint32_t kbase = sb + AKV_OFF + (nt & 1) * AKV_SZ;

        // ---- S = Q K^T  (16 rows x 128 cols per warp), pipelined ----
        float sacc[16][4];
#pragma unroll
        for (int nf = 0; nf < 16; nf++)
#pragma unroll
            for (int e = 0; e < 4; e++) sacc[nf][e] = 0.f;

        uint32_t Kf[2][2][4];   // [buf][hi/lo][4]
        {
            const uint32_t a0 = kbase + krow_b + (uint32_t)(((q8l ^ rr)) * 16);
            ldsm_x4(Kf[0][0], a0);
            ldsm_x4(Kf[0][1], a0 + 16384);
        }
#pragma unroll
        for (int stp = 0; stp < 32; stp++) {
            const int kc = stp >> 3;
            const int ng = stp & 7;
            const int cb = stp & 1;
            if (stp < 31) {
                const int kc2 = (stp + 1) >> 3, ng2 = (stp + 1) & 7;
                const uint32_t ad = kbase + krow_b + (uint32_t)(ng2 * 2048)
                                  + (uint32_t)((((kc2*2 + q8l) ^ rr)) * 16);
                ldsm_x4(Kf[cb ^ 1][0], ad);
                ldsm_x4(Kf[cb ^ 1][1], ad + 16384);
            }
            mma_bf16(sacc[ng*2],   qh_f[kc], Kf[cb][0]);
            mma_bf16(sacc[ng*2+1], qh_f[kc], Kf[cb][0] + 2);
            mma_bf16(sacc[ng*2],   qh_f[kc], Kf[cb][1]);
            mma_bf16(sacc[ng*2+1], qh_f[kc], Kf[cb][1] + 2);
            mma_bf16(sacc[ng*2],   ql_f[kc], Kf[cb][0]);
            mma_bf16(sacc[ng*2+1], ql_f[kc], Kf[cb][0] + 2);
        }

        // ---- online softmax (fully in-register, quad shfl) ----
        float m_new[2], sc[2];
#pragma unroll
        for (int er = 0; er < 2; er++) {
            float mx = -1e30f;
#pragma unroll
            for (int nf = 0; nf < 16; nf++) {
                mx = fmaxf(mx, sacc[nf][er*2]);
                mx = fmaxf(mx, sacc[nf][er*2+1]);
            }
            mx = fmaxf(mx, __shfl_xor_sync(0xffffffffu, mx, 1));
            mx = fmaxf(mx, __shfl_xor_sync(0xffffffffu, mx, 2));
            m_new[er] = fmaxf(m_i[er], mx);
            sc[er] = ex2f(m_i[er] - m_new[er]);
        }
#pragma unroll
        for (int er = 0; er < 2; er++) {
            float rs = 0.f;
#pragma unroll
            for (int nf = 0; nf < 16; nf++) {
#pragma unroll
                for (int ec = 0; ec < 2; ec++) {
                    float p = ex2f(sacc[nf][er*2+ec] - m_new[er]);
                    sacc[nf][er*2+ec] = p;
                    rs += p;
                }
            }
            rs += __shfl_xor_sync(0xffffffffu, rs, 1);
            rs += __shfl_xor_sync(0xffffffffu, rs, 2);
            l_i[er] = l_i[er] * sc[er] + rs;
            m_i[er] = m_new[er];
#pragma unroll
            for (int nf = 0; nf < 8; nf++) {
                o_acc[nf][er*2]   *= sc[er];
                o_acc[nf][er*2+1] *= sc[er];
            }
        }

        // ---- O += P V (P in registers), pipelined V frags ----
        uint32_t Vf[2][2][4];
        {
            const uint32_t a0 = kbase + 32768 + vrow_b + (uint32_t)(((q8h ^ rr)) * 16);
            ldsm_x4_t(Vf[0][0], a0);
            ldsm_x4_t(Vf[0][1], a0 + 16384);
        }
#pragma unroll
        for (int kc = 0; kc < 8; kc++) {
            uint32_t ph[4], pl[4];
            const float* cE = sacc[2*kc];
            const float* cO = sacc[2*kc+1];
            split2(cE[0], cE[1], ph[0], pl[0]);
            split2(cE[2], cE[3], ph[1], pl[1]);
            split2(cO[0], cO[1], ph[2], pl[2]);
            split2(cO[2], cO[3], ph[3], pl[3]);
#pragma unroll
            for (int ng = 0; ng < 4; ng++) {
                const int stp = kc*4 + ng;
                const int cb = stp & 1;
                if (stp < 31) {
                    const int kc2 = (stp + 1) >> 2, ng2 = (stp + 1) & 3;
                    const uint32_t ad = kbase + 32768 + vrow_b
                                      + (uint32_t)(kc2 * 2048)
                                      + (uint32_t)((((ng2*2 + q8h) ^ rr)) * 16);
                    ldsm_x4_t(Vf[cb ^ 1][0], ad);
                    ldsm_x4_t(Vf[cb ^ 1][1], ad + 16384);
                }
                mma_bf16(o_acc[ng*2],   ph, Vf[cb][0]);
                mma_bf16(o_acc[ng*2+1], ph, Vf[cb][0] + 2);
                mma_bf16(o_acc[ng*2],   pl, Vf[cb][0]);
                mma_bf16(o_acc[ng*2+1], pl, Vf[cb][0] + 2);
                mma_bf16(o_acc[ng*2],   ph, Vf[cb][1]);
                mma_bf16(o_acc[ng*2+1], ph, Vf[cb][1] + 2);
            }
        }
    }

    // ---- epilogue: per-warp direct write ----
#pragma unroll
    for (int er = 0; er < 2; er++) {
        const int r = wid*16 + (lane >> 2) + er*8;
        const float inv = 1.f / l_i[er];
        const size_t nrow = (size_t)(b*Ss + qt*128 + r) * DM + h*64;
#pragma unroll
        for (int nf = 0; nf < 8; nf++) {
            const int col = nf*8 + (lane & 3)*2;
            const float v0 = o_acc[nf][er*2]   * inv;
            const float v1 = o_acc[nf][er*2+1] * inv;
            uint32_t hp, lp;
            split2(v0, v1, hp, lp);
            *(uint32_t*)(g_Ahi + nrow + col) = hp;
            *(uint32_t*)(g_Alo + nrow + col) = lp;
        }
    }
}

// ---------------------------------------------------------------------------
extern "C" void kernel_launch(void* const* d_in, const int* in_sizes, int n_in,
                              void* d_out, int out_size)
{
    const float* x  = (const float*)d_in[0];
    const float* wq = (const float*)d_in[1];
    const float* bq = (const float*)d_in[2];
    const float* wk = (const float*)d_in[3];
    const float* bk = (const float*)d_in[4];
    const float* wv = (const float*)d_in[5];
    const float* bv = (const float*)d_in[6];
    const float* wo = (const float*)d_in[7];
    const float* bo = (const float*)d_in[8];
    float* out = (float*)d_out;

    cudaFuncSetAttribute(gemm_bf16split,
                         cudaFuncAttributeMaxDynamicSharedMemorySize, GEMM_SMEM);
    cudaFuncSetAttribute(attn_mma_kernel,
                         cudaFuncAttributeMaxDynamicSharedMemorySize, ATTN_SMEM);

    __nv_bfloat16 *gAhi, *gAlo, *gWhi, *gWlo;
    __nv_bfloat16 *gQh, *gQl, *gKh, *gKl, *gVh, *gVl;
    cudaGetSymbolAddress((void**)&gAhi, g_Ahi);
    cudaGetSymbolAddress((void**)&gAlo, g_Alo);
    cudaGetSymbolAddress((void**)&gWhi, g_Whi);
    cudaGetSymbolAddress((void**)&gWlo, g_Wlo);
    cudaGetSymbolAddress((void**)&gQh, g_Qhi);
    cudaGetSymbolAddress((void**)&gQl, g_Qlo);
    cudaGetSymbolAddress((void**)&gKh, g_Khi);
    cudaGetSymbolAddress((void**)&gKl, g_Klo);
    cudaGetSymbolAddress((void**)&gVh, g_Vhi);
    cudaGetSymbolAddress((void**)&gVl, g_Vlo);

    // 0) Split x + all 4 weights in ONE launch
    SArgs sa; sa.x = x; sa.w0 = wq; sa.w1 = wk; sa.w2 = wv; sa.w3 = wo;
    split_all_kernel<<<(XF4 + 4*WF4) / 256, 256>>>(sa, gAhi, gAlo, gWhi, gWlo);

    GArgs ga;
    ga.Ahi = gAhi; ga.Alo = gAlo; ga.Wh = gWhi; ga.Wl = gWlo;
    ga.b0 = bq; ga.b1 = bk; ga.b2 = bv; ga.b3 = bo;
    ga.outf = out;
    ga.q_h = gQh; ga.q_l = gQl; ga.k_h = gKh; ga.k_l = gKl;
    ga.v_h = gVh; ga.v_l = gVl;

    // 1) Fused Q/K/V projections (one launch, blockIdx.z selects)
    ga.mode_sel = -1;
    gemm_bf16split<<<dim3(DM/128, Nn/128, 3), 256, GEMM_SMEM>>>(ga);
    // 2) Flash attention on tensor cores (writes g_Ahi/g_Alo)
    attn_mma_kernel<<<dim3(Ss / 128, BH), 256, ATTN_SMEM>>>();
    // 3) Output projection (fp32 out)
    ga.mode_sel = 3;
    gemm_bf16split<<<dim3(DM/128, Nn/128, 1), 256, GEMM_SMEM>>>(ga);
}

// round 13
// speedup vs baseline: 2.4878x; 1.0337x over previous
#include <cuda_runtime.h>
#include <cuda_bf16.h>
#include <math.h>
#include <stdint.h>

// Problem constants
#define Bb 2
#define Ss 2048
#define DM 1024
#define Hh 16
#define Dd 64
#define Nn (Bb*Ss)          // 4096 tokens
#define BH (Bb*Hh)          // 32

#define QSCALE (0.125f * 1.4426950408889634f)   // 1/sqrt(64) * log2(e)

// Scratch (device globals)
__device__ __nv_bfloat16 g_Ahi[Nn*DM], g_Alo[Nn*DM];          // activations (x, then attn-out)
__device__ __nv_bfloat16 g_Whi[4][DM*DM], g_Wlo[4][DM*DM];    // wq, wk, wv, wo
__device__ __nv_bfloat16 g_Qhi[BH*Ss*Dd], g_Qlo[BH*Ss*Dd];    // [bh][s][d], rope'd + scaled
__device__ __nv_bfloat16 g_Khi[BH*Ss*Dd], g_Klo[BH*Ss*Dd];    // [bh][s][d], rope'd
__device__ __nv_bfloat16 g_Vhi[BH*Ss*Dd], g_Vlo[BH*Ss*Dd];    // [bh][s][d]

// ===========================================================================
// PTX helpers
// ===========================================================================
__device__ __forceinline__ uint32_t smem_u32(const void* p) {
    uint32_t a;
    asm("{ .reg .u64 t; cvta.to.shared.u64 t, %1; cvt.u32.u64 %0, t; }"
        : "=r"(a) : "l"(p));
    return a;
}

#define CP_ASYNC16(dst, src) \
    asm volatile("cp.async.cg.shared.global [%0], [%1], 16;" \
                 :: "r"(dst), "l"(src) : "memory")
#define CP_COMMIT() asm volatile("cp.async.commit_group;" ::: "memory")
#define CP_WAIT(n)  asm volatile("cp.async.wait_group %0;" :: "n"(n) : "memory")

__device__ __forceinline__ void ldsm_x4(uint32_t* r, uint32_t addr) {
    asm volatile("ldmatrix.sync.aligned.m8n8.x4.shared.b16 {%0,%1,%2,%3}, [%4];"
                 : "=r"(r[0]), "=r"(r[1]), "=r"(r[2]), "=r"(r[3]) : "r"(addr));
}
__device__ __forceinline__ void ldsm_x4_t(uint32_t* r, uint32_t addr) {
    asm volatile("ldmatrix.sync.aligned.m8n8.x4.trans.shared.b16 {%0,%1,%2,%3}, [%4];"
                 : "=r"(r[0]), "=r"(r[1]), "=r"(r[2]), "=r"(r[3]) : "r"(addr));
}
__device__ __forceinline__ void mma_bf16(float* c, const uint32_t* a,
                                         const uint32_t* b) {
    asm volatile(
        "mma.sync.aligned.m16n8k16.row.col.f32.bf16.bf16.f32 "
        "{%0,%1,%2,%3}, {%4,%5,%6,%7}, {%8,%9}, {%0,%1,%2,%3};"
        : "+f"(c[0]), "+f"(c[1]), "+f"(c[2]), "+f"(c[3])
        : "r"(a[0]), "r"(a[1]), "r"(a[2]), "r"(a[3]), "r"(b[0]), "r"(b[1]));
}
__device__ __forceinline__ float ex2f(float x) {
    float y;
    asm("ex2.approx.ftz.f32 %0, %1;" : "=f"(y) : "f"(x));
    return y;
}
// Split pair (a,b) into packed bf16x2 hi and lo (low half = a)
__device__ __forceinline__ void split2(float a, float b, uint32_t& hp, uint32_t& lp) {
    __nv_bfloat16 ha = __float2bfloat16(a), hb = __float2bfloat16(b);
    float la = a - __bfloat162float(ha);
    float lb = b - __bfloat162float(hb);
    __nv_bfloat162 hv(ha, hb);
    __nv_bfloat162 lv(__float2bfloat16(la), __float2bfloat16(lb));
    hp = *(uint32_t*)&hv;
    lp = *(uint32_t*)&lv;
}

// ===========================================================================
// Fused split: x + 4 weights -> bf16 hi/lo, one launch.
// ===========================================================================
#define XF4 (Nn*DM/4)        // 1048576 float4s
#define WF4 (DM*DM/4)        // 262144 float4s per weight

struct SArgs { const float *x, *w0, *w1, *w2, *w3; };

__global__ void split_all_kernel(SArgs s,
                                 __nv_bfloat16* __restrict__ Ahi,
                                 __nv_bfloat16* __restrict__ Alo,
                                 __nv_bfloat16* __restrict__ Whi,
                                 __nv_bfloat16* __restrict__ Wlo)
{
    const int i = blockIdx.x * blockDim.x + threadIdx.x;
    const float* src; __nv_bfloat16 *hi, *lo; int idx;
    if (i < XF4) {
        src = s.x; hi = Ahi; lo = Alo; idx = i;
    } else {
        const int j = i - XF4;
        const int w = j >> 18;            // WF4 = 2^18
        idx = j & (WF4 - 1);
        src = (w == 0) ? s.w0 : (w == 1) ? s.w1 : (w == 2) ? s.w2 : s.w3;
        hi = Whi + (size_t)w * (DM*DM);
        lo = Wlo + (size_t)w * (DM*DM);
    }
    float4 f = ((const float4*)src)[idx];
    __nv_bfloat16 h[4], l[4];
    float v[4] = {f.x, f.y, f.z, f.w};
#pragma unroll
    for (int j = 0; j < 4; j++) {
        h[j] = __float2bfloat16(v[j]);
        l[j] = __float2bfloat16(v[j] - __bfloat162float(h[j]));
    }
    ((uint2*)hi)[idx] = *(uint2*)h;
    ((uint2*)lo)[idx] = *(uint2*)l;
}

// ===========================================================================
// bf16-split GEMM (mma.sync): 128x128 tile, K-chunk 32, 2-stage, 1 sync/chunk.
// 2 CTAs/SM (64KB smem, <=128 regs).
// Stage (32KB): sA 128 rows x 128B (units 0-3 hi, 4-7 lo, swz u^(r&7))
//               sB at 16K: hi 32 krows x 256B, lo +8K, swz (u&8)|((u&7)^(r&7))
// ===========================================================================
#define GSTAGE 32768
#define GEMM_SMEM (2*GSTAGE)

struct GArgs {
    const __nv_bfloat16 *Ahi, *Alo, *Wh, *Wl;   // Wh/Wl: base of 4 matrices
    const float *b0, *b1, *b2, *b3;
    float *outf;
    __nv_bfloat16 *q_h, *q_l, *k_h, *k_l, *v_h, *v_l;
    int mode_sel;
};

__global__ __launch_bounds__(256, 2)
void gemm_bf16split(GArgs a)
{
    extern __shared__ __align__(1024) char sm[];
    const uint32_t sb = smem_u32(sm);
    const int mode = (a.mode_sel < 0) ? (int)blockIdx.z : a.mode_sel;

    const __nv_bfloat16* Whi = a.Wh + (size_t)mode * DM * DM;
    const __nv_bfloat16* Wlo = a.Wl + (size_t)mode * DM * DM;
    const float* bias = (mode == 0) ? a.b0 : (mode == 1) ? a.b1
                       : (mode == 2) ? a.b2 : a.b3;
    __nv_bfloat16* outh = (mode == 0) ? a.q_h : (mode == 1) ? a.k_h : a.v_h;
    __nv_bfloat16* outl = (mode == 0) ? a.q_l : (mode == 1) ? a.k_l : a.v_l;

    const int tid  = threadIdx.x;
    const int wid  = tid >> 5;
    const int lane = tid & 31;
    const int wm   = wid >> 1;
    const int wn   = wid & 1;
    const int row0 = blockIdx.y * 128;
    const int col0 = blockIdx.x * 128;

    // ---- cp.async assignments (8 per thread per chunk) ----
    const int a_r   = tid >> 1;            // 0..127
    const int a_u0  = (tid & 1) * 4;       // 0 (hi) or 4 (lo)
    const int b_arr = tid >> 7;            // 0 hi, 1 lo
    const int b_r   = (tid & 127) >> 2;    // 0..31
    const int b_u0  = (tid & 3) * 4;       // 0,4,8,12

    const __nv_bfloat16* aSrc =
        (a_u0 ? a.Alo : a.Ahi) + (size_t)(row0 + a_r) * DM;
    const __nv_bfloat16* bSrc =
        (b_arr ? Wlo : Whi) + (size_t)b_r * DM + col0;

    uint32_t a_dst[4], b_dst[4];
#pragma unroll
    for (int i = 0; i < 4; i++) {
        const int au = a_u0 + i;
        a_dst[i] = (uint32_t)(a_r * 128 + (au ^ (a_r & 7)) * 16);
        const int bu = b_u0 + i;
        b_dst[i] = (uint32_t)(16384 + b_arr * 8192 + b_r * 256
                              + (((bu & 8) | ((bu & 7) ^ (b_r & 7)))) * 16);
    }

    const int q8l = (lane >> 3) & 1;
    const int q8h = lane >> 4;
    const int rr  = lane & 7;

    float acc[2][8][4];
#pragma unroll
    for (int mi = 0; mi < 2; mi++)
#pragma unroll
        for (int nf = 0; nf < 8; nf++)
#pragma unroll
            for (int e = 0; e < 4; e++) acc[mi][nf][e] = 0.f;

    // ---- prologue: issue chunk 0 ----
#pragma unroll
    for (int i = 0; i < 4; i++) {
        CP_ASYNC16(sb + a_dst[i], aSrc + ((a_u0 + i) & 3) * 8);
        CP_ASYNC16(sb + b_dst[i], bSrc + (b_u0 + i) * 8);
    }
    CP_COMMIT();

    for (int c = 0; c < 32; c++) {
        CP_WAIT(0);
        __syncthreads();
        if (c + 1 < 32) {
            const uint32_t st2 = sb + ((c + 1) & 1) * GSTAGE;
            const int k0 = (c + 1) * 32;
#pragma unroll
            for (int i = 0; i < 4; i++) {
                CP_ASYNC16(st2 + a_dst[i], aSrc + k0 + ((a_u0 + i) & 3) * 8);
                CP_ASYNC16(st2 + b_dst[i], bSrc + (size_t)k0 * DM + (b_u0 + i) * 8);
            }
            CP_COMMIT();
        }

        const uint32_t st = sb + (c & 1) * GSTAGE;
#pragma unroll
        for (int s = 0; s < 2; s++) {
            uint32_t ah[2][4], al[2][4];
#pragma unroll
            for (int mi = 0; mi < 2; mi++) {
                const int arow = wm * 32 + mi * 16 + q8l * 8 + rr;
                const uint32_t oh = (uint32_t)(arow * 128
                                   + ((2*s + q8h) ^ (arow & 7)) * 16);
                const uint32_t ol = (uint32_t)(arow * 128
                                   + ((4 + 2*s + q8h) ^ (arow & 7)) * 16);
                ldsm_x4(ah[mi], st + oh);
                ldsm_x4(al[mi], st + ol);
            }
#pragma unroll
            for (int ng = 0; ng < 4; ng++) {
                const int krow = 16 * s + q8l * 8 + rr;
                const int u = wn * 8 + ng * 2 + q8h;
                const uint32_t ob = (uint32_t)(16384 + krow * 256
                                  + (((u & 8) | ((u & 7) ^ (krow & 7)))) * 16);
                uint32_t bh4[4], bl4[4];
                ldsm_x4_t(bh4, st + ob);
                ldsm_x4_t(bl4, st + ob + 8192);
#pragma unroll
                for (int mi = 0; mi < 2; mi++) {
                    mma_bf16(acc[mi][ng*2],   ah[mi], bh4);
                    mma_bf16(acc[mi][ng*2+1], ah[mi], bh4 + 2);
                    mma_bf16(acc[mi][ng*2],   ah[mi], bl4);
                    mma_bf16(acc[mi][ng*2+1], ah[mi], bl4 + 2);
                    mma_bf16(acc[mi][ng*2],   al[mi], bh4);
                    mma_bf16(acc[mi][ng*2+1], al[mi], bh4 + 2);
                }
            }
        }
    }

    // --- epilogue ----------------------------------------------------------
    float bias_v[16];
#pragma unroll
    for (int nf = 0; nf < 8; nf++)
#pragma unroll
        for (int ec = 0; ec < 2; ec++)
            bias_v[nf*2 + ec] = __ldg(&bias[col0 + wn*64 + nf*8 + (lane&3)*2 + ec]);

    float invf[8];
    if (mode < 2) {
#pragma unroll
        for (int nf = 0; nf < 4; nf++)
#pragma unroll
            for (int ec = 0; ec < 2; ec++) {
                const int j = nf*8 + (lane&3)*2 + ec;
                invf[nf*2 + ec] = powf(10000.f, -(float)j / 32.f);
            }
    }
    const int h_idx = blockIdx.x * 2 + wn;
    const float oscale = (mode == 0) ? QSCALE : 1.f;

#pragma unroll
    for (int mi = 0; mi < 2; mi++) {
#pragma unroll
        for (int er = 0; er < 2; er++) {
            const int m = wm*32 + mi*16 + (lane >> 2) + er*8;
            const int n = row0 + m;
            const int b = n >> 11;
            const int s = n & 2047;
            if (mode < 2) {
                float y1[8], y2[8];
#pragma unroll
                for (int nf = 0; nf < 4; nf++)
#pragma unroll
                    for (int ec = 0; ec < 2; ec++) {
                        const int ii = nf*2 + ec;
                        float sn, cs;
                        sincosf((float)s * invf[ii], &sn, &cs);
                        const float x1 = acc[mi][nf][er*2 + ec]   + bias_v[ii];
                        const float x2 = acc[mi][nf+4][er*2 + ec] + bias_v[ii + 8];
                        y1[ii] = (x1 * cs - x2 * sn) * oscale;
                        y2[ii] = (x2 * cs + x1 * sn) * oscale;
                    }
                __nv_bfloat16* dh = outh + (((size_t)(b*Hh + h_idx))*Ss + s)*Dd;
                __nv_bfloat16* dl = outl + (((size_t)(b*Hh + h_idx))*Ss + s)*Dd;
#pragma unroll
                for (int nf = 0; nf < 4; nf++) {
                    const int d = nf*8 + (lane&3)*2;
                    uint32_t hp, lp;
                    split2(y1[nf*2], y1[nf*2+1], hp, lp);
                    *(uint32_t*)(dh + d) = hp; *(uint32_t*)(dl + d) = lp;
                    split2(y2[nf*2], y2[nf*2+1], hp, lp);
                    *(uint32_t*)(dh + d + 32) = hp; *(uint32_t*)(dl + d + 32) = lp;
                }
            } else if (mode == 2) {
                __nv_bfloat16* dh = outh + (((size_t)(b*Hh + h_idx))*Ss + s)*Dd;
                __nv_bfloat16* dl = outl + (((size_t)(b*Hh + h_idx))*Ss + s)*Dd;
#pragma unroll
                for (int nf = 0; nf < 8; nf++) {
                    const int d = nf*8 + (lane&3)*2;
                    uint32_t hp, lp;
                    split2(acc[mi][nf][er*2] + bias_v[nf*2],
                           acc[mi][nf][er*2+1] + bias_v[nf*2+1], hp, lp);
                    *(uint32_t*)(dh + d) = hp; *(uint32_t*)(dl + d) = lp;
                }
            } else {
                float* dst = a.outf + (size_t)n * DM + col0 + wn*64;
#pragma unroll
                for (int nf = 0; nf < 8; nf++)
#pragma unroll
                    for (int ec = 0; ec < 2; ec++)
                        dst[nf*8 + (lane&3)*2 + ec] =
                            acc[mi][nf][er*2 + ec] + bias_v[nf*2 + ec];
            }
        }
    }
}

// ===========================================================================
// Flash attention on mma.sync, FA2-style warp-row ownership, KV tile 64,
// 2 CTAs/SM (96KB smem, <=128 regs). Q frags reloaded from smem per tile.
// smem: Qhi 16K | Qlo 16K | 2 KV stages of 32K (Khi 8K|Klo 8K|Vhi 8K|Vlo 8K)
// ===========================================================================
#define AQ_OFF    0
#define AKV_OFF   32768
#define AKV_SZ    32768
#define ATTN_SMEM (AKV_OFF + 2*AKV_SZ)    // 98304

__global__ __launch_bounds__(256, 2)
void attn_mma_kernel()
{
    extern __shared__ __align__(1024) char sm[];
    const uint32_t sb = smem_u32(sm);
    const int tid  = threadIdx.x;
    const int wid  = tid >> 5;
    const int lane = tid & 31;
    const int qt   = blockIdx.x;
    const int bh   = blockIdx.y;
    const int b    = bh >> 4;
    const int h    = bh & 15;

    const int q8l = (lane >> 3) & 1;
    const int q8h = lane >> 4;
    const int rr  = lane & 7;

    // cp.async assignments
    const int ca  = tid >> 7;          // 0 = hi array, 1 = lo array
    const int ct  = tid & 127;         // Q row
    const int kr  = ct >> 1;           // KV row 0..63
    const int kh0 = (ct & 1) * 4;      // unit base for K/V
    const __nv_bfloat16* gq = (ca ? g_Qlo : g_Qhi) + ((size_t)bh*Ss + qt*128 + ct)*Dd;
    const __nv_bfloat16* gk = (ca ? g_Klo : g_Khi) + ((size_t)bh*Ss + kr)*Dd;
    const __nv_bfloat16* gv = (ca ? g_Vlo : g_Vhi) + ((size_t)bh*Ss + kr)*Dd;

    const uint32_t qb0 = (uint32_t)(AQ_OFF + ca*16384 + ct*128);
    uint32_t kdst[4], vdst[4];
#pragma unroll
    for (int i = 0; i < 4; i++) {
        const int u = kh0 + i;
        const uint32_t sw = (uint32_t)((u ^ (kr & 7)) * 16);
        kdst[i] = (uint32_t)(ca*8192 + kr*128) + sw;
        vdst[i] = (uint32_t)(16384 + ca*8192 + kr*128) + sw;
    }

    // ldmatrix lane bases
    const uint32_t qrow_b = (uint32_t)((wid*16 + q8l*8 + rr) * 128);  // Q a-frag rows
    const uint32_t krow_b = (uint32_t)((q8h*8 + rr) * 128);           // K b-frag rows
    const uint32_t vrow_b = (uint32_t)((q8l*8 + rr) * 128);           // V b-frag rows

    // prologue: load Q + tile 0
#pragma unroll
    for (int u = 0; u < 8; u++)
        CP_ASYNC16(sb + qb0 + (uint32_t)((u ^ (ct & 7)) * 16), gq + u*8);
#pragma unroll
    for (int i = 0; i < 4; i++) {
        CP_ASYNC16(sb + AKV_OFF + kdst[i], gk + (kh0 + i)*8);
        CP_ASYNC16(sb + AKV_OFF + vdst[i], gv + (kh0 + i)*8);
    }
    CP_COMMIT();

    float o_acc[8][4];
    float m_i[2], l_i[2];
#pragma unroll
    for (int er = 0; er < 2; er++) { m_i[er] = -1e30f; l_i[er] = 0.f; }
#pragma unroll
    for (int nf = 0; nf < 8; nf++)
#pragma unroll
        for (int e = 0; e < 4; e++) o_acc[nf][e] = 0.f;

    for (int nt = 0; nt < 32; nt++) {
        CP_WAIT(0);
        __syncthreads();

        if (nt + 1 < 32) {
            const uint32_t kb = sb + AKV_OFF + ((nt + 1) & 1) * AKV_SZ;
            const size_t s0 = (size_t)(nt + 1) * 64 * Dd;
#pragma unroll
            for (int i = 0; i < 4; i++) {
                CP_ASYNC16(kb + kdst[i], gk + s0 + (kh0 + i)*8);
                CP_ASYNC16(kb + vdst[i], gv + s0 + (kh0 + i)*8);
            }
            CP_COMMIT();
        }

        const uint32_t kbase = sb + AKV_OFF + (nt & 1) * AKV_SZ;

        // ---- S = Q K^T  (16 rows x 64 cols per warp) ----
        float sacc[8][4];
#pragma unroll
        for (int nf = 0; nf < 8; nf++)
#pragma unroll
            for (int e = 0; e < 4; e++) sacc[nf][e] = 0.f;

#pragma unroll
        for (int kc = 0; kc < 4; kc++) {
            uint32_t qh_f[4], ql_f[4];
            const uint32_t qa = sb + AQ_OFF + qrow_b
                              + (uint32_t)(((kc*2 + q8h) ^ rr) * 16);
            ldsm_x4(qh_f, qa);
            ldsm_x4(ql_f, qa + 16384);
#pragma unroll
            for (int ng = 0; ng < 4; ng++) {
                const uint32_t ko = kbase + (uint32_t)(ng * 2048) + krow_b
                                  + (uint32_t)(((kc*2 + q8l) ^ rr) * 16);
                uint32_t kh4[4], kl4[4];
                ldsm_x4(kh4, ko);
                ldsm_x4(kl4, ko + 8192);
                mma_bf16(sacc[ng*2],   qh_f, kh4);
                mma_bf16(sacc[ng*2+1], qh_f, kh4 + 2);
                mma_bf16(sacc[ng*2],   qh_f, kl4);
                mma_bf16(sacc[ng*2+1], qh_f, kl4 + 2);
                mma_bf16(sacc[ng*2],   ql_f, kh4);
                mma_bf16(sacc[ng*2+1], ql_f, kh4 + 2);
            }
        }

        // ---- online softmax (in-register, quad shfl) ----
        float m_new[2], sc[2];
#pragma unroll
        for (int er = 0; er < 2; er++) {
            float mx = -1e30f;
#pragma unroll
            for (int nf = 0; nf < 8; nf++) {
                mx = fmaxf(mx, sacc[nf][er*2]);
                mx = fmaxf(mx, sacc[nf][er*2+1]);
            }
            mx = fmaxf(mx, __shfl_xor_sync(0xffffffffu, mx, 1));
            mx = fmaxf(mx, __shfl_xor_sync(0xffffffffu, mx, 2));
            m_new[er] = fmaxf(m_i[er], mx);
            sc[er] = ex2f(m_i[er] - m_new[er]);
        }
#pragma unroll
        for (int er = 0; er < 2; er++) {
            float rs = 0.f;
#pragma unroll
            for (int nf = 0; nf < 8; nf++) {
#pragma unroll
                for (int ec = 0; ec < 2; ec++) {
                    float p = ex2f(sacc[nf][er*2+ec] - m_new[er]);
                    sacc[nf][er*2+ec] = p;
                    rs += p;
                }
            }
            rs += __shfl_xor_sync(0xffffffffu, rs, 1);
            rs += __shfl_xor_sync(0xffffffffu, rs, 2);
            l_i[er] = l_i[er] * sc[er] + rs;
            m_i[er] = m_new[er];
#pragma unroll
            for (int nf = 0; nf < 8; nf++) {
                o_acc[nf][er*2]   *= sc[er];
                o_acc[nf][er*2+1] *= sc[er];
            }
        }

        // ---- O += P V ----
#pragma unroll
        for (int kc = 0; kc < 4; kc++) {
            uint32_t ph[4], pl[4];
            const float* cE = sacc[2*kc];
            const float* cO = sacc[2*kc+1];
            split2(cE[0], cE[1], ph[0], pl[0]);
            split2(cE[2], cE[3], ph[1], pl[1]);
            split2(cO[0], cO[1], ph[2], pl[2]);
            split2(cO[2], cO[3], ph[3], pl[3]);
#pragma unroll
            for (int ng = 0; ng < 4; ng++) {
                const uint32_t vo = kbase + 16384 + (uint32_t)(kc * 2048) + vrow_b
                                  + (uint32_t)(((ng*2 + q8h) ^ rr) * 16);
                uint32_t vh[4], vl[4];
                ldsm_x4_t(vh, vo);
                ldsm_x4_t(vl, vo + 8192);
                mma_bf16(o_acc[ng*2],   ph, vh);
                mma_bf16(o_acc[ng*2+1], ph, vh + 2);
                mma_bf16(o_acc[ng*2],   pl, vh);
                mma_bf16(o_acc[ng*2+1], pl, vh + 2);
                mma_bf16(o_acc[ng*2],   ph, vl);
                mma_bf16(o_acc[ng*2+1], ph, vl + 2);
            }
        }
    }

    // ---- epilogue: per-warp direct write ----
#pragma unroll
    for (int er = 0; er < 2; er++) {
        const int r = wid*16 + (lane >> 2) + er*8;
        const float inv = 1.f / l_i[er];
        const size_t nrow = (size_t)(b*Ss + qt*128 + r) * DM + h*64;
#pragma unroll
        for (int nf = 0; nf < 8; nf++) {
            const int col = nf*8 + (lane & 3)*2;
            const float v0 = o_acc[nf][er*2]   * inv;
            const float v1 = o_acc[nf][er*2+1] * inv;
            uint32_t hp, lp;
            split2(v0, v1, hp, lp);
            *(uint32_t*)(g_Ahi + nrow + col) = hp;
            *(uint32_t*)(g_Alo + nrow + col) = lp;
        }
    }
}

// ---------------------------------------------------------------------------
extern "C" void kernel_launch(void* const* d_in, const int* in_sizes, int n_in,
                              void* d_out, int out_size)
{
    const float* x  = (const float*)d_in[0];
    const float* wq = (const float*)d_in[1];
    const float* bq = (const float*)d_in[2];
    const float* wk = (const float*)d_in[3];
    const float* bk = (const float*)d_in[4];
    const float* wv = (const float*)d_in[5];
    const float* bv = (const float*)d_in[6];
    const float* wo = (const float*)d_in[7];
    const float* bo = (const float*)d_in[8];
    float* out = (float*)d_out;

    cudaFuncSetAttribute(gemm_bf16split,
                         cudaFuncAttributeMaxDynamicSharedMemorySize, GEMM_SMEM);
    cudaFuncSetAttribute(attn_mma_kernel,
                         cudaFuncAttributeMaxDynamicSharedMemorySize, ATTN_SMEM);

    __nv_bfloat16 *gAhi, *gAlo, *gWhi, *gWlo;
    __nv_bfloat16 *gQh, *gQl, *gKh, *gKl, *gVh, *gVl;
    cudaGetSymbolAddress((void**)&gAhi, g_Ahi);
    cudaGetSymbolAddress((void**)&gAlo, g_Alo);
    cudaGetSymbolAddress((void**)&gWhi, g_Whi);
    cudaGetSymbolAddress((void**)&gWlo, g_Wlo);
    cudaGetSymbolAddress((void**)&gQh, g_Qhi);
    cudaGetSymbolAddress((void**)&gQl, g_Qlo);
    cudaGetSymbolAddress((void**)&gKh, g_Khi);
    cudaGetSymbolAddress((void**)&gKl, g_Klo);
    cudaGetSymbolAddress((void**)&gVh, g_Vhi);
    cudaGetSymbolAddress((void**)&gVl, g_Vlo);

    // 0) Split x + all 4 weights in ONE launch
    SArgs sa; sa.x = x; sa.w0 = wq; sa.w1 = wk; sa.w2 = wv; sa.w3 = wo;
    split_all_kernel<<<(XF4 + 4*WF4) / 256, 256>>>(sa, gAhi, gAlo, gWhi, gWlo);

    GArgs ga;
    ga.Ahi = gAhi; ga.Alo = gAlo; ga.Wh = gWhi; ga.Wl = gWlo;
    ga.b0 = bq; ga.b1 = bk; ga.b2 = bv; ga.b3 = bo;
    ga.outf = out;
    ga.q_h = gQh; ga.q_l = gQl; ga.k_h = gKh; ga.k_l = gKl;
    ga.v_h = gVh; ga.v_l = gVl;

    // 1) Fused Q/K/V projections (one launch, blockIdx.z selects)
    ga.mode_sel = -1;
    gemm_bf16split<<<dim3(DM/128, Nn/128, 3), 256, GEMM_SMEM>>>(ga);
    // 2) Flash attention on tensor cores (writes g_Ahi/g_Alo)
    attn_mma_kernel<<<dim3(Ss / 128, BH), 256, ATTN_SMEM>>>();
    // 3) Output projection (fp32 out)
    ga.mode_sel = 3;
    gemm_bf16split<<<dim3(DM/128, Nn/128, 1), 256, GEMM_SMEM>>>(ga);
}